// round 11
// baseline (speedup 1.0000x reference)
#include <cuda_runtime.h>
#include <cstdint>
#include <math.h>

#define BB 2
#define SS 2048
#define HH 768
#define NHH 12
#define HDD 64
#define WPR 384   // bf16-pair words per 768-row

// Packed bf16 hi/lo global scratch (allocation-free rule: __device__ globals)
__device__ uint32_t g_Xh[4096*WPR],  g_Xl[4096*WPR];
__device__ uint32_t g_WTh[4*HH*WPR], g_WTl[4*HH*WPR];   // [z][n][kpair]
__device__ uint32_t g_Qh[24*SS*32],  g_Ql[24*SS*32];    // [bh][s][dpair] (pre-scaled 0.125)
__device__ uint32_t g_Kh[24*SS*32],  g_Kl[24*SS*32];    // [bh][s][dpair]
__device__ uint32_t g_Vh[24*64*1024], g_Vl[24*64*1024]; // [bh][d][kvpair]
__device__ uint32_t g_Ch[4096*WPR],  g_Cl[4096*WPR];    // ctx packed

// ---------------------------------------------------------------------------
// Helpers
// ---------------------------------------------------------------------------
__device__ __forceinline__ uint32_t smem_u32(const void* p) {
    uint32_t a;
    asm("{ .reg .u64 t; cvta.to.shared.u64 t, %1; cvt.u32.u64 %0, t; }" : "=r"(a) : "l"(p));
    return a;
}

__device__ __forceinline__ void packbf2(float x0, float x1, uint32_t& hw, uint32_t& lw) {
    uint32_t h;
    asm("cvt.rn.bf16x2.f32 %0, %1, %2;" : "=r"(h) : "f"(x1), "f"(x0));
    float h0 = __uint_as_float(h << 16);
    float h1 = __uint_as_float(h & 0xFFFF0000u);
    asm("cvt.rn.bf16x2.f32 %0, %1, %2;" : "=r"(lw) : "f"(x1 - h1), "f"(x0 - h0));
    hw = h;
}

__device__ __forceinline__ void mmabf2(float d[4], const uint32_t a[4], uint32_t b0, uint32_t b1) {
    asm volatile(
        "mma.sync.aligned.m16n8k16.row.col.f32.bf16.bf16.f32 "
        "{%0,%1,%2,%3}, {%4,%5,%6,%7}, {%8,%9}, {%0,%1,%2,%3};"
        : "+f"(d[0]), "+f"(d[1]), "+f"(d[2]), "+f"(d[3])
        : "r"(a[0]), "r"(a[1]), "r"(a[2]), "r"(a[3]), "r"(b0), "r"(b1));
}

__device__ __forceinline__ void ldsm4(uint32_t r[4], uint32_t addr) {
    asm volatile("ldmatrix.sync.aligned.m8n8.x4.shared.b16 {%0,%1,%2,%3}, [%4];"
        : "=r"(r[0]), "=r"(r[1]), "=r"(r[2]), "=r"(r[3]) : "r"(addr));
}

__device__ __forceinline__ void cpa16(uint32_t saddr, const void* g) {
    asm volatile("cp.async.cg.shared.global [%0], [%1], 16;" :: "r"(saddr), "l"(g));
}
#define CPA_COMMIT() asm volatile("cp.async.commit_group;" ::: "memory")
#define CPA_WAIT1()  asm volatile("cp.async.wait_group 1;" ::: "memory")
#define CPA_WAIT0()  asm volatile("cp.async.wait_group 0;" ::: "memory")

// exp(x) without MUFU; clamp handles -10000 masked scores
__device__ __forceinline__ float fexp(float x) {
    x = fmaxf(x, -87.0f);
    const float L2E = 1.4426950408889634f;
    float z = fmaf(x, L2E, 12582912.0f);
    int   n = (__float_as_int(z) & 0x7FFFFF) - 0x400000;
    float r = z - 12582912.0f;
    float f = fmaf(x, L2E, -r);
    float y =              1.3333558e-3f;
    y = fmaf(y, f, 9.6181291e-3f);
    y = fmaf(y, f, 5.5504109e-2f);
    y = fmaf(y, f, 2.4022649e-1f);
    y = fmaf(y, f, 6.9314718e-1f);
    y = fmaf(y, f, 1.0f);
    return y * __int_as_float((n + 127) << 23);
}

// ---------------------------------------------------------------------------
// Prep kernels
// ---------------------------------------------------------------------------
__global__ void pack_x(const float* __restrict__ X) {
    int i = blockIdx.x * 256 + threadIdx.x;
    const int n = 4096 * WPR;
    for (int w = i; w < n; w += gridDim.x * 256) {
        float2 v = ((const float2*)X)[w];
        packbf2(v.x, v.y, g_Xh[w], g_Xl[w]);
    }
}

__global__ void transpose_pack_w(const float* __restrict__ W0, const float* __restrict__ W1,
                                 const float* __restrict__ W2, const float* __restrict__ W3) {
    __shared__ float t[32][33];
    int z = blockIdx.z;
    const float* W = z == 0 ? W0 : z == 1 ? W1 : z == 2 ? W2 : W3;
    uint32_t* WTh = g_WTh + (size_t)z * HH * WPR;
    uint32_t* WTl = g_WTl + (size_t)z * HH * WPR;
    int bx = blockIdx.x * 32, by = blockIdx.y * 32;
    int tx = threadIdx.x, ty = threadIdx.y;
    #pragma unroll
    for (int i = 0; i < 4; i++)
        t[ty + 8*i][tx] = W[(size_t)(by + ty + 8*i) * HH + bx + tx];
    __syncthreads();
    int li = ty * 32 + tx;
    #pragma unroll
    for (int it = 0; it < 2; it++) {
        int q = li + it * 256;
        int n_l = q >> 4, w = q & 15;
        uint32_t hw, lw;
        packbf2(t[2*w][n_l], t[2*w + 1][n_l], hw, lw);
        size_t addr = (size_t)(bx + n_l) * WPR + (by >> 1) + w;
        WTh[addr] = hw; WTl[addr] = lw;
    }
}

// ---------------------------------------------------------------------------
// Projection GEMM (2xBF16 m16n8k16), double-buffered, ldmatrix fragments.
// ---------------------------------------------------------------------------
#define W_BIAS 15360
#define W_COS  15424
#define W_SIN  15488
#define GEMM_SMEM (15552*4)

__device__ __forceinline__ void gemm_main(const uint32_t* __restrict__ Ahg,
                                          const uint32_t* __restrict__ Alg,
                                          const uint32_t* __restrict__ Bhg,
                                          const uint32_t* __restrict__ Blg,
                                          int m0, int n0, uint32_t* smw,
                                          float acc[2][4][4]) {
    const int tid = threadIdx.x;
    const int wid = tid >> 5, lane = tid & 31;
    const int wm = wid >> 1, wn = wid & 1;
    const int ar = tid >> 2, au = tid & 3;
    const int so0 = ar*20 + au*4, so1 = (ar + 64)*20 + au*4;
    const uint32_t sb = smem_u32(smw);

    const int l8 = (lane >> 3) & 1, l16 = lane >> 4, l7 = lane & 7;
    const int aoff0 = (wm*32 +        l8*8 + l7)*20 + l16*4;
    const int aoff1 = aoff0 + 16*20;
    const int boff0 = (wn*32 +        l16*8 + l7)*20 + l8*4;
    const int boff1 = boff0 + 16*20;

    const uint32_t* pA0h = Ahg + (size_t)(m0 + ar) * WPR + au*4;
    const uint32_t* pA1h = pA0h + (size_t)64 * WPR;
    const uint32_t* pA0l = Alg + (size_t)(m0 + ar) * WPR + au*4;
    const uint32_t* pA1l = pA0l + (size_t)64 * WPR;
    const uint32_t* pBh  = Bhg + (size_t)(n0 + ar) * WPR + au*4;
    const uint32_t* pBl  = Blg + (size_t)(n0 + ar) * WPR + au*4;

    uint4 a0h = *(const uint4*)pA0h, a1h = *(const uint4*)pA1h;
    uint4 a0l = *(const uint4*)pA0l, a1l = *(const uint4*)pA1l;
    uint4 b0h = *(const uint4*)pBh,  b0l = *(const uint4*)pBl;
    *(uint4*)(smw + so0)         = a0h; *(uint4*)(smw + so1)         = a1h;
    *(uint4*)(smw + 2560 + so0)  = a0l; *(uint4*)(smw + 2560 + so1)  = a1l;
    *(uint4*)(smw + 10240 + so0) = b0h;
    *(uint4*)(smw + 11520 + so0) = b0l;

    for (int kb = 0; kb < 24; kb++) {
        const int cur = kb & 1;
        if (kb < 23) {
            int ko = (kb + 1) * 16;
            a0h = *(const uint4*)(pA0h + ko); a1h = *(const uint4*)(pA1h + ko);
            a0l = *(const uint4*)(pA0l + ko); a1l = *(const uint4*)(pA1l + ko);
            b0h = *(const uint4*)(pBh + ko);  b0l = *(const uint4*)(pBl + ko);
        }
        __syncthreads();
        const int AH = cur*5120, AL = AH + 2560;
        const int BH = 10240 + cur*2560, BL = BH + 1280;
        #pragma unroll
        for (int ks = 0; ks < 2; ks++) {
            int kk = ks * 8;
            uint32_t ah0[4], ah1[4], al0[4], al1[4];
            uint32_t bh0[4], bh1[4], bl0[4], bl1[4];
            ldsm4(ah0, sb + (AH + aoff0 + kk)*4);
            ldsm4(ah1, sb + (AH + aoff1 + kk)*4);
            ldsm4(al0, sb + (AL + aoff0 + kk)*4);
            ldsm4(al1, sb + (AL + aoff1 + kk)*4);
            ldsm4(bh0, sb + (BH + boff0 + kk)*4);
            ldsm4(bh1, sb + (BH + boff1 + kk)*4);
            ldsm4(bl0, sb + (BL + boff0 + kk)*4);
            ldsm4(bl1, sb + (BL + boff1 + kk)*4);
            mmabf2(acc[0][0], al0, bh0[0], bh0[1]); mmabf2(acc[0][1], al0, bh0[2], bh0[3]);
            mmabf2(acc[0][2], al0, bh1[0], bh1[1]); mmabf2(acc[0][3], al0, bh1[2], bh1[3]);
            mmabf2(acc[1][0], al1, bh0[0], bh0[1]); mmabf2(acc[1][1], al1, bh0[2], bh0[3]);
            mmabf2(acc[1][2], al1, bh1[0], bh1[1]); mmabf2(acc[1][3], al1, bh1[2], bh1[3]);
            mmabf2(acc[0][0], ah0, bl0[0], bl0[1]); mmabf2(acc[0][1], ah0, bl0[2], bl0[3]);
            mmabf2(acc[0][2], ah0, bl1[0], bl1[1]); mmabf2(acc[0][3], ah0, bl1[2], bl1[3]);
            mmabf2(acc[1][0], ah1, bl0[0], bl0[1]); mmabf2(acc[1][1], ah1, bl0[2], bl0[3]);
            mmabf2(acc[1][2], ah1, bl1[0], bl1[1]); mmabf2(acc[1][3], ah1, bl1[2], bl1[3]);
            mmabf2(acc[0][0], ah0, bh0[0], bh0[1]); mmabf2(acc[0][1], ah0, bh0[2], bh0[3]);
            mmabf2(acc[0][2], ah0, bh1[0], bh1[1]); mmabf2(acc[0][3], ah0, bh1[2], bh1[3]);
            mmabf2(acc[1][0], ah1, bh0[0], bh0[1]); mmabf2(acc[1][1], ah1, bh0[2], bh0[3]);
            mmabf2(acc[1][2], ah1, bh1[0], bh1[1]); mmabf2(acc[1][3], ah1, bh1[2], bh1[3]);
        }
        if (kb < 23) {
            const int nxt = (1 - cur) * 5120;
            const int nxb = 10240 + (1 - cur) * 2560;
            *(uint4*)(smw + nxt + so0)        = a0h; *(uint4*)(smw + nxt + so1)        = a1h;
            *(uint4*)(smw + nxt + 2560 + so0) = a0l; *(uint4*)(smw + nxt + 2560 + so1) = a1l;
            *(uint4*)(smw + nxb + so0)        = b0h;
            *(uint4*)(smw + nxb + 1280 + so0) = b0l;
        }
    }
    __syncthreads();
}

__device__ __forceinline__ void stage_acc(uint32_t* smw, float acc[2][4][4]) {
    const int tid = threadIdx.x;
    const int wid = tid >> 5, lane = tid & 31, g = lane >> 2, c = lane & 3;
    const int wm = wid >> 1, wn = wid & 1;
    float* Sg = (float*)smw;
    #pragma unroll
    for (int mt = 0; mt < 2; mt++) {
        int r0 = wm*32 + mt*16 + g;
        #pragma unroll
        for (int nt = 0; nt < 4; nt++) {
            int col = wn*32 + nt*8 + 2*c;
            *(float2*)&Sg[r0*66 + col]       = make_float2(acc[mt][nt][0], acc[mt][nt][1]);
            *(float2*)&Sg[(r0 + 8)*66 + col] = make_float2(acc[mt][nt][2], acc[mt][nt][3]);
        }
    }
    __syncthreads();
}

// ---------------------------------------------------------------------------
// QKV projection + bias + RoPE (head-indexed, faithful), packed outputs.
// Q is pre-scaled by 0.125 (1/sqrt(64)) here — exact power-of-2.
// ---------------------------------------------------------------------------
__global__ __launch_bounds__(256, 2)
void qkv_pk(const float* __restrict__ bq, const float* __restrict__ bk,
            const float* __restrict__ bv,
            const float* __restrict__ cosp, const float* __restrict__ sinp) {
    extern __shared__ uint32_t smw[];
    int tid = threadIdx.x;
    int z = blockIdx.z;
    int m0 = blockIdx.y * 128, n0 = blockIdx.x * 64;
    const float* bias = z == 0 ? bq : z == 1 ? bk : bv;

    if (tid < 64) {
        ((float*)(smw + W_BIAS))[tid] = bias[n0 + tid];
        ((float*)(smw + W_COS ))[tid] = cosp[n0 + tid];
        ((float*)(smw + W_SIN ))[tid] = sinp[n0 + tid];
    }
    float acc[2][4][4] = {};
    size_t zo = (size_t)z * HH * WPR;
    gemm_main(g_Xh, g_Xl, g_WTh + zo, g_WTl + zo, m0, n0, smw, acc);
    stage_acc(smw, acc);

    float* Sg = (float*)smw;
    const float* sBias = (const float*)(smw + W_BIAS);
    const float* sCos  = (const float*)(smw + W_COS);
    const float* sSin  = (const float*)(smw + W_SIN);
    int m = tid >> 1;
    int half = (tid & 1) * 32;
    int mg = m0 + m;
    int bbt = mg >> 11, s = mg & 2047;
    int h = blockIdx.x;
    int bh = bbt * NHH + h;

    float o[32];
    if (z < 2) {
        float qsc = (z == 0) ? 0.125f : 1.0f;
        #pragma unroll
        for (int i = 0; i < 32; i++) {
            int cg = half + i;
            float v = Sg[m*66 + cg] + sBias[cg];
            int pc = (cg < 32) ? (2*cg + 1) : (2*(cg - 32));
            float pv = Sg[m*66 + pc] + sBias[pc];
            float sgn = (cg < 32) ? -1.0f : 1.0f;
            o[i] = (v * sCos[cg] + sgn * pv * sSin[cg]) * qsc;
        }
        uint32_t* Dh = (z == 0 ? g_Qh : g_Kh) + ((size_t)bh * SS + s) * 32 + (tid & 1) * 16;
        uint32_t* Dl = (z == 0 ? g_Ql : g_Kl) + ((size_t)bh * SS + s) * 32 + (tid & 1) * 16;
        #pragma unroll
        for (int j = 0; j < 16; j++) {
            uint32_t hw, lw;
            packbf2(o[2*j], o[2*j + 1], hw, lw);
            Dh[j] = hw; Dl[j] = lw;
        }
    } else {
        #pragma unroll
        for (int i = 0; i < 32; i++)
            o[i] = Sg[m*66 + half + i] + sBias[half + i];
        size_t base = (size_t)bh * 64 * 1024 + ((m0 & 2047) >> 1) + (tid >> 2);
        #pragma unroll
        for (int i = 0; i < 32; i++) {
            float pv = __shfl_down_sync(0xFFFFFFFFu, o[i], 2);
            if (!(tid & 2)) {
                uint32_t hw, lw;
                packbf2(o[i], pv, hw, lw);
                g_Vh[base + (size_t)(half + i) * 1024] = hw;
                g_Vl[base + (size_t)(half + i) * 1024] = lw;
            }
        }
    }
}

__global__ __launch_bounds__(256, 2)
void o_pk(const float* __restrict__ bo, float* __restrict__ out) {
    extern __shared__ uint32_t smw[];
    int tid = threadIdx.x;
    int m0 = blockIdx.y * 128, n0 = blockIdx.x * 64;
    if (tid < 64) ((float*)(smw + W_BIAS))[tid] = bo[n0 + tid];

    float acc[2][4][4] = {};
    size_t zo = (size_t)3 * HH * WPR;
    gemm_main(g_Ch, g_Cl, g_WTh + zo, g_WTl + zo, m0, n0, smw, acc);
    stage_acc(smw, acc);

    float* Sg = (float*)smw;
    const float* sBias = (const float*)(smw + W_BIAS);
    int m = tid >> 1;
    int half = (tid & 1) * 32;
    float* dst = out + (size_t)(m0 + m) * HH + n0 + half;
    #pragma unroll
    for (int i4 = 0; i4 < 8; i4++) {
        float4 v;
        v.x = Sg[m*66 + half + i4*4 + 0] + sBias[half + i4*4 + 0];
        v.y = Sg[m*66 + half + i4*4 + 1] + sBias[half + i4*4 + 1];
        v.z = Sg[m*66 + half + i4*4 + 2] + sBias[half + i4*4 + 2];
        v.w = Sg[m*66 + half + i4*4 + 3] + sBias[half + i4*4 + 3];
        *(float4*)(dst + i4*4) = v;
    }
}

// ---------------------------------------------------------------------------
// Flash attention v5: 2 CTAs/SM. Q persistent in smem (re-LDSM per tile so
// Q fragments don't stay live through PV), double-buffered cp.async K/V
// (2 syncs/tile; the co-resident CTA fills barrier bubbles), pack folded into
// the PV loop to cut pah/pal liveness. launch_bounds(256,2) caps regs at 128.
// smem words: buf q at q*9216 {KH,KL,VH,VL}; QH 18432, QL 23040;
// mask 27648 + q*64. Total 27840 w = 111.36 KB -> 2 CTAs/SM (222.7 <= 227).
// grid (16, 24): 384 blocks / 296 slots = 1.3 waves (was 2.6).
// ---------------------------------------------------------------------------
#define FV_BUF(q) ((q)*9216)
#define FV_QH 18432
#define FV_QL 23040
#define FV_MSB(q) (27648 + (q)*64)
#define FLASH_SMEM (27840*4)

__global__ __launch_bounds__(256, 2)
void flash_pk(const float* __restrict__ mask) {
    extern __shared__ uint32_t smw[];
    const uint32_t sb = smem_u32(smw);
    int bh = blockIdx.y;
    int b = bh / NHH, h = bh % NHH;
    int sq0 = blockIdx.x * 128;
    const float* mkg = mask + (size_t)b * SS;
    int tid = threadIdx.x;
    int wid = tid >> 5, lane = tid & 31, g = lane >> 2, c = lane & 3;
    const int l8 = (lane >> 3) & 1, l16 = lane >> 4, l7 = lane & 7;

    const uint32_t* Khg0 = g_Kh + (size_t)bh * SS * 32;
    const uint32_t* Klg0 = g_Kl + (size_t)bh * SS * 32;
    const uint32_t* Vhg0 = g_Vh + (size_t)bh * 64 * 1024;
    const uint32_t* Vlg0 = g_Vl + (size_t)bh * 64 * 1024;
    const int cr = tid >> 3, cu = tid & 7;   // staging row/quad

    const int qoff = (wid*16 + l8*8 + l7)*36 + l16*4;
    int koff[4];
    #pragma unroll
    for (int t = 0; t < 4; t++)
        koff[t] = (t*16 + l16*8 + l7)*36 + l8*4;   // same formula for K and V

    // prologue: issue K/V tile 0 into buf0 (async)
    {
        uint32_t kb = FV_BUF(0);
        #pragma unroll
        for (int it = 0; it < 2; it++) {
            int r = cr + it*32;
            uint32_t wo = (r*36 + cu*4)*4;
            cpa16(sb + kb*4          + wo, Khg0 + r*32 + cu*4);
            cpa16(sb + (kb + 2304)*4 + wo, Klg0 + r*32 + cu*4);
            cpa16(sb + (kb + 4608)*4 + wo, Vhg0 + (size_t)r*1024 + cu*4);
            cpa16(sb + (kb + 6912)*4 + wo, Vlg0 + (size_t)r*1024 + cu*4);
        }
        if (tid < 16) cpa16(sb + (FV_MSB(0) + tid*4)*4, mkg + tid*4);
        CPA_COMMIT();
    }

    // stage Q (128 rows) into persistent smem region
    {
        const uint32_t* Qhg = g_Qh + ((size_t)bh * SS + sq0) * 32;
        const uint32_t* Qlg = g_Ql + ((size_t)bh * SS + sq0) * 32;
        #pragma unroll
        for (int it = 0; it < 4; it++) {
            int idx = tid + it * 256;
            int r = idx >> 3, u = idx & 7;
            *(uint4*)(smw + FV_QH + r*36 + u*4) = *(const uint4*)(Qhg + r*32 + u*4);
            *(uint4*)(smw + FV_QL + r*36 + u*4) = *(const uint4*)(Qlg + r*32 + u*4);
        }
    }

    float oa[8][4] = {};
    float l0r = 0.0f, l1r = 0.0f;   // per-lane partial row sums

    for (int jt = 0; jt < 32; jt++) {
        const int cur = jt & 1;
        __syncthreads();   // compute on buf[1-cur] (jt-1) done; Q stores visible at jt=0
        if (jt < 31) {
            int jn = jt + 1;
            uint32_t kb = FV_BUF(1 - cur);
            const uint32_t* Khg = Khg0 + (size_t)jn*64*32 + cr*32 + cu*4;
            const uint32_t* Klg = Klg0 + (size_t)jn*64*32 + cr*32 + cu*4;
            const uint32_t* Vhg = Vhg0 + jn*32 + (size_t)cr*1024 + cu*4;
            const uint32_t* Vlg = Vlg0 + jn*32 + (size_t)cr*1024 + cu*4;
            #pragma unroll
            for (int it = 0; it < 2; it++) {
                int r = cr + it*32;
                uint32_t wo = (r*36 + cu*4)*4;
                cpa16(sb + kb*4          + wo, Khg + it*32*32);
                cpa16(sb + (kb + 2304)*4 + wo, Klg + it*32*32);
                cpa16(sb + (kb + 4608)*4 + wo, Vhg + (size_t)it*32*1024);
                cpa16(sb + (kb + 6912)*4 + wo, Vlg + (size_t)it*32*1024);
            }
            if (tid < 16) cpa16(sb + (FV_MSB(1 - cur) + tid*4)*4, mkg + jn*64 + tid*4);
        }
        CPA_COMMIT();
        if (jt < 31) CPA_WAIT1(); else CPA_WAIT0();
        __syncthreads();   // tile jt data visible to all threads

        const uint32_t KHb = FV_BUF(cur), KLb = KHb + 2304;
        const uint32_t VHb = KHb + 4608,  VLb = KHb + 6912;
        const float* msf = (const float*)(smw + FV_MSB(cur));

        // --- S = Q @ K^T (Q fragments re-lifted per tile; die after QK) ---
        float sv[8][4] = {};
        #pragma unroll
        for (int ks = 0; ks < 4; ks++) {
            int kk = ks * 8;
            uint32_t qh[4], ql[4];
            ldsm4(qh, sb + (FV_QH + qoff + kk)*4);
            ldsm4(ql, sb + (FV_QL + qoff + kk)*4);
            #pragma unroll
            for (int t = 0; t < 4; t++) {
                uint32_t bhf[4], blf[4];
                ldsm4(bhf, sb + (KHb + koff[t] + kk)*4);
                ldsm4(blf, sb + (KLb + koff[t] + kk)*4);
                mmabf2(sv[2*t],   ql, bhf[0], bhf[1]);
                mmabf2(sv[2*t+1], ql, bhf[2], bhf[3]);
                mmabf2(sv[2*t],   qh, blf[0], blf[1]);
                mmabf2(sv[2*t+1], qh, blf[2], blf[3]);
                mmabf2(sv[2*t],   qh, bhf[0], bhf[1]);
                mmabf2(sv[2*t+1], qh, bhf[2], bhf[3]);
            }
        }

        // --- no-max softmax: e = exp(s + mask_add), accumulate lane sums ---
        #pragma unroll
        for (int nt = 0; nt < 8; nt++) {
            int col = nt*8 + 2*c;
            float ma = fmaf(msf[col],     10000.0f, -10000.0f);
            float mb = fmaf(msf[col + 1], 10000.0f, -10000.0f);
            sv[nt][0] = fexp(sv[nt][0] + ma); l0r += sv[nt][0];
            sv[nt][1] = fexp(sv[nt][1] + mb); l0r += sv[nt][1];
            sv[nt][2] = fexp(sv[nt][2] + ma); l1r += sv[nt][2];
            sv[nt][3] = fexp(sv[nt][3] + mb); l1r += sv[nt][3];
        }

        // --- O += P @ V; pack P per-ks inside the loop (short pah/pal life) ---
        #pragma unroll
        for (int ks = 0; ks < 4; ks++) {
            uint32_t pah[4], pal[4];
            packbf2(sv[2*ks][0],   sv[2*ks][1],   pah[0], pal[0]);
            packbf2(sv[2*ks][2],   sv[2*ks][3],   pah[1], pal[1]);
            packbf2(sv[2*ks+1][0], sv[2*ks+1][1], pah[2], pal[2]);
            packbf2(sv[2*ks+1][2], sv[2*ks+1][3], pah[3], pal[3]);
            int kk = ks * 8;
            #pragma unroll
            for (int t = 0; t < 4; t++) {
                uint32_t vh[4], vl[4];
                ldsm4(vh, sb + (VHb + koff[t] + kk)*4);
                ldsm4(vl, sb + (VLb + koff[t] + kk)*4);
                mmabf2(oa[2*t],   pal, vh[0], vh[1]);
                mmabf2(oa[2*t+1], pal, vh[2], vh[3]);
                mmabf2(oa[2*t],   pah, vl[0], vl[1]);
                mmabf2(oa[2*t+1], pah, vl[2], vl[3]);
                mmabf2(oa[2*t],   pah, vh[0], vh[1]);
                mmabf2(oa[2*t+1], pah, vh[2], vh[3]);
            }
        }
    }

    // --- close lane sums (deferred), normalize, write ctx packed ---
    l0r += __shfl_xor_sync(0xFFFFFFFFu, l0r, 1);
    l0r += __shfl_xor_sync(0xFFFFFFFFu, l0r, 2);
    l1r += __shfl_xor_sync(0xFFFFFFFFu, l1r, 1);
    l1r += __shfl_xor_sync(0xFFFFFFFFu, l1r, 2);
    float inv0 = 1.0f / l0r, inv1 = 1.0f / l1r;
    int sA = sq0 + wid*16 + g, sB = sA + 8;
    size_t baseA = ((size_t)(b*SS + sA)) * WPR + h*32;
    size_t baseB = ((size_t)(b*SS + sB)) * WPR + h*32;
    #pragma unroll
    for (int nch = 0; nch < 8; nch++) {
        uint32_t hw, lw;
        packbf2(oa[nch][0] * inv0, oa[nch][1] * inv0, hw, lw);
        g_Ch[baseA + nch*4 + c] = hw; g_Cl[baseA + nch*4 + c] = lw;
        packbf2(oa[nch][2] * inv1, oa[nch][3] * inv1, hw, lw);
        g_Ch[baseB + nch*4 + c] = hw; g_Cl[baseB + nch*4 + c] = lw;
    }
}

extern "C" void kernel_launch(void* const* d_in, const int* in_sizes, int n_in,
                              void* d_out, int out_size) {
    const float* hs   = (const float*)d_in[0];
    const float* mask = (const float*)d_in[1];
    const float* Wq   = (const float*)d_in[2];
    const float* bq   = (const float*)d_in[3];
    const float* Wk   = (const float*)d_in[4];
    const float* bk   = (const float*)d_in[5];
    const float* Wv   = (const float*)d_in[6];
    const float* bv   = (const float*)d_in[7];
    const float* Wo   = (const float*)d_in[8];
    const float* bo   = (const float*)d_in[9];
    const float* cosp = (const float*)d_in[10];
    const float* sinp = (const float*)d_in[11];
    float* out = (float*)d_out;

    cudaFuncSetAttribute(qkv_pk,   cudaFuncAttributeMaxDynamicSharedMemorySize, GEMM_SMEM);
    cudaFuncSetAttribute(o_pk,     cudaFuncAttributeMaxDynamicSharedMemorySize, GEMM_SMEM);
    cudaFuncSetAttribute(flash_pk, cudaFuncAttributeMaxDynamicSharedMemorySize, FLASH_SMEM);

    pack_x<<<768, 256>>>(hs);
    transpose_pack_w<<<dim3(24, 24, 4), dim3(32, 8)>>>(Wq, Wk, Wv, Wo);
    qkv_pk<<<dim3(12, 32, 3), 256, GEMM_SMEM>>>(bq, bk, bv, cosp, sinp);
    flash_pk<<<dim3(16, 24), 256, FLASH_SMEM>>>(mask);
    o_pk<<<dim3(12, 32), 256, GEMM_SMEM>>>(bo, out);
}

// round 12
// speedup vs baseline: 1.0530x; 1.0530x over previous
#include <cuda_runtime.h>
#include <cstdint>
#include <math.h>

#define BB 2
#define SS 2048
#define HH 768
#define NHH 12
#define HDD 64
#define WPR 384   // bf16-pair words per 768-row

// Packed bf16 hi/lo global scratch (allocation-free rule: __device__ globals)
__device__ uint32_t g_Xh[4096*WPR],  g_Xl[4096*WPR];
__device__ uint32_t g_WTh[4*HH*WPR], g_WTl[4*HH*WPR];   // [z][n][kpair]
__device__ uint32_t g_Qh[24*SS*32],  g_Ql[24*SS*32];    // [bh][s][dpair] (pre-scaled 0.125*log2e)
__device__ uint32_t g_Kh[24*SS*32],  g_Kl[24*SS*32];    // [bh][s][dpair]
__device__ uint32_t g_Vh[24*64*1024], g_Vl[24*64*1024]; // [bh][d][kvpair]
__device__ uint32_t g_Ch[4096*WPR],  g_Cl[4096*WPR];    // ctx packed

// ---------------------------------------------------------------------------
// Helpers
// ---------------------------------------------------------------------------
__device__ __forceinline__ uint32_t smem_u32(const void* p) {
    uint32_t a;
    asm("{ .reg .u64 t; cvta.to.shared.u64 t, %1; cvt.u32.u64 %0, t; }" : "=r"(a) : "l"(p));
    return a;
}

__device__ __forceinline__ void packbf2(float x0, float x1, uint32_t& hw, uint32_t& lw) {
    uint32_t h;
    asm("cvt.rn.bf16x2.f32 %0, %1, %2;" : "=r"(h) : "f"(x1), "f"(x0));
    float h0 = __uint_as_float(h << 16);
    float h1 = __uint_as_float(h & 0xFFFF0000u);
    asm("cvt.rn.bf16x2.f32 %0, %1, %2;" : "=r"(lw) : "f"(x1 - h1), "f"(x0 - h0));
    hw = h;
}

__device__ __forceinline__ void mmabf2(float d[4], const uint32_t a[4], uint32_t b0, uint32_t b1) {
    asm volatile(
        "mma.sync.aligned.m16n8k16.row.col.f32.bf16.bf16.f32 "
        "{%0,%1,%2,%3}, {%4,%5,%6,%7}, {%8,%9}, {%0,%1,%2,%3};"
        : "+f"(d[0]), "+f"(d[1]), "+f"(d[2]), "+f"(d[3])
        : "r"(a[0]), "r"(a[1]), "r"(a[2]), "r"(a[3]), "r"(b0), "r"(b1));
}

__device__ __forceinline__ void ldsm4(uint32_t r[4], uint32_t addr) {
    asm volatile("ldmatrix.sync.aligned.m8n8.x4.shared.b16 {%0,%1,%2,%3}, [%4];"
        : "=r"(r[0]), "=r"(r[1]), "=r"(r[2]), "=r"(r[3]) : "r"(addr));
}

__device__ __forceinline__ void cpa16(uint32_t saddr, const void* g) {
    asm volatile("cp.async.cg.shared.global [%0], [%1], 16;" :: "r"(saddr), "l"(g));
}
#define CPA_COMMIT() asm volatile("cp.async.commit_group;" ::: "memory")
#define CPA_WAIT1()  asm volatile("cp.async.wait_group 1;" ::: "memory")
#define CPA_WAIT0()  asm volatile("cp.async.wait_group 0;" ::: "memory")

// 2^x via MUFU (1 instruction). Scores are pre-scaled by log2(e) upstream, so
// ex2(s) == exp(s_orig). Masked scores ~-14427 underflow cleanly to 0.
__device__ __forceinline__ float fex2(float x) {
    float r;
    asm("ex2.approx.f32 %0, %1;" : "=f"(r) : "f"(x));
    return r;
}

// ---------------------------------------------------------------------------
// Prep kernels
// ---------------------------------------------------------------------------
__global__ void pack_x(const float* __restrict__ X) {
    int i = blockIdx.x * 256 + threadIdx.x;
    const int n = 4096 * WPR;
    for (int w = i; w < n; w += gridDim.x * 256) {
        float2 v = ((const float2*)X)[w];
        packbf2(v.x, v.y, g_Xh[w], g_Xl[w]);
    }
}

__global__ void transpose_pack_w(const float* __restrict__ W0, const float* __restrict__ W1,
                                 const float* __restrict__ W2, const float* __restrict__ W3) {
    __shared__ float t[32][33];
    int z = blockIdx.z;
    const float* W = z == 0 ? W0 : z == 1 ? W1 : z == 2 ? W2 : W3;
    uint32_t* WTh = g_WTh + (size_t)z * HH * WPR;
    uint32_t* WTl = g_WTl + (size_t)z * HH * WPR;
    int bx = blockIdx.x * 32, by = blockIdx.y * 32;
    int tx = threadIdx.x, ty = threadIdx.y;
    #pragma unroll
    for (int i = 0; i < 4; i++)
        t[ty + 8*i][tx] = W[(size_t)(by + ty + 8*i) * HH + bx + tx];
    __syncthreads();
    int li = ty * 32 + tx;
    #pragma unroll
    for (int it = 0; it < 2; it++) {
        int q = li + it * 256;
        int n_l = q >> 4, w = q & 15;
        uint32_t hw, lw;
        packbf2(t[2*w][n_l], t[2*w + 1][n_l], hw, lw);
        size_t addr = (size_t)(bx + n_l) * WPR + (by >> 1) + w;
        WTh[addr] = hw; WTl[addr] = lw;
    }
}

// ---------------------------------------------------------------------------
// Projection GEMM (2xBF16 m16n8k16), double-buffered, ldmatrix fragments.
// ---------------------------------------------------------------------------
#define W_BIAS 15360
#define W_COS  15424
#define W_SIN  15488
#define GEMM_SMEM (15552*4)

__device__ __forceinline__ void gemm_main(const uint32_t* __restrict__ Ahg,
                                          const uint32_t* __restrict__ Alg,
                                          const uint32_t* __restrict__ Bhg,
                                          const uint32_t* __restrict__ Blg,
                                          int m0, int n0, uint32_t* smw,
                                          float acc[2][4][4]) {
    const int tid = threadIdx.x;
    const int wid = tid >> 5, lane = tid & 31;
    const int wm = wid >> 1, wn = wid & 1;
    const int ar = tid >> 2, au = tid & 3;
    const int so0 = ar*20 + au*4, so1 = (ar + 64)*20 + au*4;
    const uint32_t sb = smem_u32(smw);

    const int l8 = (lane >> 3) & 1, l16 = lane >> 4, l7 = lane & 7;
    const int aoff0 = (wm*32 +        l8*8 + l7)*20 + l16*4;
    const int aoff1 = aoff0 + 16*20;
    const int boff0 = (wn*32 +        l16*8 + l7)*20 + l8*4;
    const int boff1 = boff0 + 16*20;

    const uint32_t* pA0h = Ahg + (size_t)(m0 + ar) * WPR + au*4;
    const uint32_t* pA1h = pA0h + (size_t)64 * WPR;
    const uint32_t* pA0l = Alg + (size_t)(m0 + ar) * WPR + au*4;
    const uint32_t* pA1l = pA0l + (size_t)64 * WPR;
    const uint32_t* pBh  = Bhg + (size_t)(n0 + ar) * WPR + au*4;
    const uint32_t* pBl  = Blg + (size_t)(n0 + ar) * WPR + au*4;

    uint4 a0h = *(const uint4*)pA0h, a1h = *(const uint4*)pA1h;
    uint4 a0l = *(const uint4*)pA0l, a1l = *(const uint4*)pA1l;
    uint4 b0h = *(const uint4*)pBh,  b0l = *(const uint4*)pBl;
    *(uint4*)(smw + so0)         = a0h; *(uint4*)(smw + so1)         = a1h;
    *(uint4*)(smw + 2560 + so0)  = a0l; *(uint4*)(smw + 2560 + so1)  = a1l;
    *(uint4*)(smw + 10240 + so0) = b0h;
    *(uint4*)(smw + 11520 + so0) = b0l;

    for (int kb = 0; kb < 24; kb++) {
        const int cur = kb & 1;
        if (kb < 23) {
            int ko = (kb + 1) * 16;
            a0h = *(const uint4*)(pA0h + ko); a1h = *(const uint4*)(pA1h + ko);
            a0l = *(const uint4*)(pA0l + ko); a1l = *(const uint4*)(pA1l + ko);
            b0h = *(const uint4*)(pBh + ko);  b0l = *(const uint4*)(pBl + ko);
        }
        __syncthreads();
        const int AH = cur*5120, AL = AH + 2560;
        const int BH = 10240 + cur*2560, BL = BH + 1280;
        #pragma unroll
        for (int ks = 0; ks < 2; ks++) {
            int kk = ks * 8;
            uint32_t ah0[4], ah1[4], al0[4], al1[4];
            uint32_t bh0[4], bh1[4], bl0[4], bl1[4];
            ldsm4(ah0, sb + (AH + aoff0 + kk)*4);
            ldsm4(ah1, sb + (AH + aoff1 + kk)*4);
            ldsm4(al0, sb + (AL + aoff0 + kk)*4);
            ldsm4(al1, sb + (AL + aoff1 + kk)*4);
            ldsm4(bh0, sb + (BH + boff0 + kk)*4);
            ldsm4(bh1, sb + (BH + boff1 + kk)*4);
            ldsm4(bl0, sb + (BL + boff0 + kk)*4);
            ldsm4(bl1, sb + (BL + boff1 + kk)*4);
            mmabf2(acc[0][0], al0, bh0[0], bh0[1]); mmabf2(acc[0][1], al0, bh0[2], bh0[3]);
            mmabf2(acc[0][2], al0, bh1[0], bh1[1]); mmabf2(acc[0][3], al0, bh1[2], bh1[3]);
            mmabf2(acc[1][0], al1, bh0[0], bh0[1]); mmabf2(acc[1][1], al1, bh0[2], bh0[3]);
            mmabf2(acc[1][2], al1, bh1[0], bh1[1]); mmabf2(acc[1][3], al1, bh1[2], bh1[3]);
            mmabf2(acc[0][0], ah0, bl0[0], bl0[1]); mmabf2(acc[0][1], ah0, bl0[2], bl0[3]);
            mmabf2(acc[0][2], ah0, bl1[0], bl1[1]); mmabf2(acc[0][3], ah0, bl1[2], bl1[3]);
            mmabf2(acc[1][0], ah1, bl0[0], bl0[1]); mmabf2(acc[1][1], ah1, bl0[2], bl0[3]);
            mmabf2(acc[1][2], ah1, bl1[0], bl1[1]); mmabf2(acc[1][3], ah1, bl1[2], bl1[3]);
            mmabf2(acc[0][0], ah0, bh0[0], bh0[1]); mmabf2(acc[0][1], ah0, bh0[2], bh0[3]);
            mmabf2(acc[0][2], ah0, bh1[0], bh1[1]); mmabf2(acc[0][3], ah0, bh1[2], bh1[3]);
            mmabf2(acc[1][0], ah1, bh0[0], bh0[1]); mmabf2(acc[1][1], ah1, bh0[2], bh0[3]);
            mmabf2(acc[1][2], ah1, bh1[0], bh1[1]); mmabf2(acc[1][3], ah1, bh1[2], bh1[3]);
        }
        if (kb < 23) {
            const int nxt = (1 - cur) * 5120;
            const int nxb = 10240 + (1 - cur) * 2560;
            *(uint4*)(smw + nxt + so0)        = a0h; *(uint4*)(smw + nxt + so1)        = a1h;
            *(uint4*)(smw + nxt + 2560 + so0) = a0l; *(uint4*)(smw + nxt + 2560 + so1) = a1l;
            *(uint4*)(smw + nxb + so0)        = b0h;
            *(uint4*)(smw + nxb + 1280 + so0) = b0l;
        }
    }
    __syncthreads();
}

__device__ __forceinline__ void stage_acc(uint32_t* smw, float acc[2][4][4]) {
    const int tid = threadIdx.x;
    const int wid = tid >> 5, lane = tid & 31, g = lane >> 2, c = lane & 3;
    const int wm = wid >> 1, wn = wid & 1;
    float* Sg = (float*)smw;
    #pragma unroll
    for (int mt = 0; mt < 2; mt++) {
        int r0 = wm*32 + mt*16 + g;
        #pragma unroll
        for (int nt = 0; nt < 4; nt++) {
            int col = wn*32 + nt*8 + 2*c;
            *(float2*)&Sg[r0*66 + col]       = make_float2(acc[mt][nt][0], acc[mt][nt][1]);
            *(float2*)&Sg[(r0 + 8)*66 + col] = make_float2(acc[mt][nt][2], acc[mt][nt][3]);
        }
    }
    __syncthreads();
}

// ---------------------------------------------------------------------------
// QKV projection + bias + RoPE (head-indexed, faithful), packed outputs.
// Q pre-scaled by 0.125*log2(e) so flash softmax is a bare ex2.
// ---------------------------------------------------------------------------
__global__ __launch_bounds__(256, 2)
void qkv_pk(const float* __restrict__ bq, const float* __restrict__ bk,
            const float* __restrict__ bv,
            const float* __restrict__ cosp, const float* __restrict__ sinp) {
    extern __shared__ uint32_t smw[];
    int tid = threadIdx.x;
    int z = blockIdx.z;
    int m0 = blockIdx.y * 128, n0 = blockIdx.x * 64;
    const float* bias = z == 0 ? bq : z == 1 ? bk : bv;

    if (tid < 64) {
        ((float*)(smw + W_BIAS))[tid] = bias[n0 + tid];
        ((float*)(smw + W_COS ))[tid] = cosp[n0 + tid];
        ((float*)(smw + W_SIN ))[tid] = sinp[n0 + tid];
    }
    float acc[2][4][4] = {};
    size_t zo = (size_t)z * HH * WPR;
    gemm_main(g_Xh, g_Xl, g_WTh + zo, g_WTl + zo, m0, n0, smw, acc);
    stage_acc(smw, acc);

    float* Sg = (float*)smw;
    const float* sBias = (const float*)(smw + W_BIAS);
    const float* sCos  = (const float*)(smw + W_COS);
    const float* sSin  = (const float*)(smw + W_SIN);
    int m = tid >> 1;
    int half = (tid & 1) * 32;
    int mg = m0 + m;
    int bbt = mg >> 11, s = mg & 2047;
    int h = blockIdx.x;
    int bh = bbt * NHH + h;

    float o[32];
    if (z < 2) {
        // 0.125 * log2(e): folds softmax's exp->ex2 conversion into Q.
        float qsc = (z == 0) ? 0.18033688011112042f : 1.0f;
        #pragma unroll
        for (int i = 0; i < 32; i++) {
            int cg = half + i;
            float v = Sg[m*66 + cg] + sBias[cg];
            int pc = (cg < 32) ? (2*cg + 1) : (2*(cg - 32));
            float pv = Sg[m*66 + pc] + sBias[pc];
            float sgn = (cg < 32) ? -1.0f : 1.0f;
            o[i] = (v * sCos[cg] + sgn * pv * sSin[cg]) * qsc;
        }
        uint32_t* Dh = (z == 0 ? g_Qh : g_Kh) + ((size_t)bh * SS + s) * 32 + (tid & 1) * 16;
        uint32_t* Dl = (z == 0 ? g_Ql : g_Kl) + ((size_t)bh * SS + s) * 32 + (tid & 1) * 16;
        #pragma unroll
        for (int j = 0; j < 16; j++) {
            uint32_t hw, lw;
            packbf2(o[2*j], o[2*j + 1], hw, lw);
            Dh[j] = hw; Dl[j] = lw;
        }
    } else {
        #pragma unroll
        for (int i = 0; i < 32; i++)
            o[i] = Sg[m*66 + half + i] + sBias[half + i];
        size_t base = (size_t)bh * 64 * 1024 + ((m0 & 2047) >> 1) + (tid >> 2);
        #pragma unroll
        for (int i = 0; i < 32; i++) {
            float pv = __shfl_down_sync(0xFFFFFFFFu, o[i], 2);
            if (!(tid & 2)) {
                uint32_t hw, lw;
                packbf2(o[i], pv, hw, lw);
                g_Vh[base + (size_t)(half + i) * 1024] = hw;
                g_Vl[base + (size_t)(half + i) * 1024] = lw;
            }
        }
    }
}

__global__ __launch_bounds__(256, 2)
void o_pk(const float* __restrict__ bo, float* __restrict__ out) {
    extern __shared__ uint32_t smw[];
    int tid = threadIdx.x;
    int m0 = blockIdx.y * 128, n0 = blockIdx.x * 64;
    if (tid < 64) ((float*)(smw + W_BIAS))[tid] = bo[n0 + tid];

    float acc[2][4][4] = {};
    size_t zo = (size_t)3 * HH * WPR;
    gemm_main(g_Ch, g_Cl, g_WTh + zo, g_WTl + zo, m0, n0, smw, acc);
    stage_acc(smw, acc);

    float* Sg = (float*)smw;
    const float* sBias = (const float*)(smw + W_BIAS);
    int m = tid >> 1;
    int half = (tid & 1) * 32;
    float* dst = out + (size_t)(m0 + m) * HH + n0 + half;
    #pragma unroll
    for (int i4 = 0; i4 < 8; i4++) {
        float4 v;
        v.x = Sg[m*66 + half + i4*4 + 0] + sBias[half + i4*4 + 0];
        v.y = Sg[m*66 + half + i4*4 + 1] + sBias[half + i4*4 + 1];
        v.z = Sg[m*66 + half + i4*4 + 2] + sBias[half + i4*4 + 2];
        v.w = Sg[m*66 + half + i4*4 + 3] + sBias[half + i4*4 + 3];
        *(float4*)(dst + i4*4) = v;
    }
}

// ---------------------------------------------------------------------------
// Flash attention v6: softmax via single-MUFU ex2 (log2e folded into Q and
// the mask constant). 2 CTAs/SM, Q persistent in smem, double-buffered
// cp.async K/V, pack folded into PV loop. 2 syncs/tile.
// smem words: buf q at q*9216 {KH,KL,VH,VL}; QH 18432, QL 23040;
// mask 27648 + q*64. Total 27840 w = 111.36 KB -> 2 CTAs/SM.
// ---------------------------------------------------------------------------
#define FV_BUF(q) ((q)*9216)
#define FV_QH 18432
#define FV_QL 23040
#define FV_MSB(q) (27648 + (q)*64)
#define FLASH_SMEM (27840*4)

__global__ __launch_bounds__(256, 2)
void flash_pk(const float* __restrict__ mask) {
    extern __shared__ uint32_t smw[];
    const uint32_t sb = smem_u32(smw);
    int bh = blockIdx.y;
    int b = bh / NHH, h = bh % NHH;
    int sq0 = blockIdx.x * 128;
    const float* mkg = mask + (size_t)b * SS;
    int tid = threadIdx.x;
    int wid = tid >> 5, lane = tid & 31, g = lane >> 2, c = lane & 3;
    const int l8 = (lane >> 3) & 1, l16 = lane >> 4, l7 = lane & 7;

    const uint32_t* Khg0 = g_Kh + (size_t)bh * SS * 32;
    const uint32_t* Klg0 = g_Kl + (size_t)bh * SS * 32;
    const uint32_t* Vhg0 = g_Vh + (size_t)bh * 64 * 1024;
    const uint32_t* Vlg0 = g_Vl + (size_t)bh * 64 * 1024;
    const int cr = tid >> 3, cu = tid & 7;   // staging row/quad

    const int qoff = (wid*16 + l8*8 + l7)*36 + l16*4;
    int koff[4];
    #pragma unroll
    for (int t = 0; t < 4; t++)
        koff[t] = (t*16 + l16*8 + l7)*36 + l8*4;   // same formula for K and V

    // prologue: issue K/V tile 0 into buf0 (async)
    {
        uint32_t kb = FV_BUF(0);
        #pragma unroll
        for (int it = 0; it < 2; it++) {
            int r = cr + it*32;
            uint32_t wo = (r*36 + cu*4)*4;
            cpa16(sb + kb*4          + wo, Khg0 + r*32 + cu*4);
            cpa16(sb + (kb + 2304)*4 + wo, Klg0 + r*32 + cu*4);
            cpa16(sb + (kb + 4608)*4 + wo, Vhg0 + (size_t)r*1024 + cu*4);
            cpa16(sb + (kb + 6912)*4 + wo, Vlg0 + (size_t)r*1024 + cu*4);
        }
        if (tid < 16) cpa16(sb + (FV_MSB(0) + tid*4)*4, mkg + tid*4);
        CPA_COMMIT();
    }

    // stage Q (128 rows) into persistent smem region
    {
        const uint32_t* Qhg = g_Qh + ((size_t)bh * SS + sq0) * 32;
        const uint32_t* Qlg = g_Ql + ((size_t)bh * SS + sq0) * 32;
        #pragma unroll
        for (int it = 0; it < 4; it++) {
            int idx = tid + it * 256;
            int r = idx >> 3, u = idx & 7;
            *(uint4*)(smw + FV_QH + r*36 + u*4) = *(const uint4*)(Qhg + r*32 + u*4);
            *(uint4*)(smw + FV_QL + r*36 + u*4) = *(const uint4*)(Qlg + r*32 + u*4);
        }
    }

    float oa[8][4] = {};
    float l0r = 0.0f, l1r = 0.0f;   // per-lane partial row sums

    for (int jt = 0; jt < 32; jt++) {
        const int cur = jt & 1;
        __syncthreads();   // compute on buf[1-cur] (jt-1) done; Q stores visible at jt=0
        if (jt < 31) {
            int jn = jt + 1;
            uint32_t kb = FV_BUF(1 - cur);
            const uint32_t* Khg = Khg0 + (size_t)jn*64*32 + cr*32 + cu*4;
            const uint32_t* Klg = Klg0 + (size_t)jn*64*32 + cr*32 + cu*4;
            const uint32_t* Vhg = Vhg0 + jn*32 + (size_t)cr*1024 + cu*4;
            const uint32_t* Vlg = Vlg0 + jn*32 + (size_t)cr*1024 + cu*4;
            #pragma unroll
            for (int it = 0; it < 2; it++) {
                int r = cr + it*32;
                uint32_t wo = (r*36 + cu*4)*4;
                cpa16(sb + kb*4          + wo, Khg + it*32*32);
                cpa16(sb + (kb + 2304)*4 + wo, Klg + it*32*32);
                cpa16(sb + (kb + 4608)*4 + wo, Vhg + (size_t)it*32*1024);
                cpa16(sb + (kb + 6912)*4 + wo, Vlg + (size_t)it*32*1024);
            }
            if (tid < 16) cpa16(sb + (FV_MSB(1 - cur) + tid*4)*4, mkg + jn*64 + tid*4);
        }
        CPA_COMMIT();
        if (jt < 31) CPA_WAIT1(); else CPA_WAIT0();
        __syncthreads();   // tile jt data visible to all threads

        const uint32_t KHb = FV_BUF(cur), KLb = KHb + 2304;
        const uint32_t VHb = KHb + 4608,  VLb = KHb + 6912;
        const float* msf = (const float*)(smw + FV_MSB(cur));

        // --- S = Q @ K^T (scores already in log2 domain via Q pre-scale) ---
        float sv[8][4] = {};
        #pragma unroll
        for (int ks = 0; ks < 4; ks++) {
            int kk = ks * 8;
            uint32_t qh[4], ql[4];
            ldsm4(qh, sb + (FV_QH + qoff + kk)*4);
            ldsm4(ql, sb + (FV_QL + qoff + kk)*4);
            #pragma unroll
            for (int t = 0; t < 4; t++) {
                uint32_t bhf[4], blf[4];
                ldsm4(bhf, sb + (KHb + koff[t] + kk)*4);
                ldsm4(blf, sb + (KLb + koff[t] + kk)*4);
                mmabf2(sv[2*t],   ql, bhf[0], bhf[1]);
                mmabf2(sv[2*t+1], ql, bhf[2], bhf[3]);
                mmabf2(sv[2*t],   qh, blf[0], blf[1]);
                mmabf2(sv[2*t+1], qh, blf[2], blf[3]);
                mmabf2(sv[2*t],   qh, bhf[0], bhf[1]);
                mmabf2(sv[2*t+1], qh, bhf[2], bhf[3]);
            }
        }

        // --- softmax: p = ex2(s + mask_log2), accumulate lane sums ---
        // mask_log2 = (1-mask)*(-10000)*log2(e) = mask*14426.95 - 14426.95
        #pragma unroll
        for (int nt = 0; nt < 8; nt++) {
            int col = nt*8 + 2*c;
            float ma = fmaf(msf[col],     14426.950408889634f, -14426.950408889634f);
            float mb = fmaf(msf[col + 1], 14426.950408889634f, -14426.950408889634f);
            sv[nt][0] = fex2(sv[nt][0] + ma); l0r += sv[nt][0];
            sv[nt][1] = fex2(sv[nt][1] + mb); l0r += sv[nt][1];
            sv[nt][2] = fex2(sv[nt][2] + ma); l1r += sv[nt][2];
            sv[nt][3] = fex2(sv[nt][3] + mb); l1r += sv[nt][3];
        }

        // --- O += P @ V; pack P per-ks inside the loop (short pah/pal life) ---
        #pragma unroll
        for (int ks = 0; ks < 4; ks++) {
            uint32_t pah[4], pal[4];
            packbf2(sv[2*ks][0],   sv[2*ks][1],   pah[0], pal[0]);
            packbf2(sv[2*ks][2],   sv[2*ks][3],   pah[1], pal[1]);
            packbf2(sv[2*ks+1][0], sv[2*ks+1][1], pah[2], pal[2]);
            packbf2(sv[2*ks+1][2], sv[2*ks+1][3], pah[3], pal[3]);
            int kk = ks * 8;
            #pragma unroll
            for (int t = 0; t < 4; t++) {
                uint32_t vh[4], vl[4];
                ldsm4(vh, sb + (VHb + koff[t] + kk)*4);
                ldsm4(vl, sb + (VLb + koff[t] + kk)*4);
                mmabf2(oa[2*t],   pal, vh[0], vh[1]);
                mmabf2(oa[2*t+1], pal, vh[2], vh[3]);
                mmabf2(oa[2*t],   pah, vl[0], vl[1]);
                mmabf2(oa[2*t+1], pah, vl[2], vl[3]);
                mmabf2(oa[2*t],   pah, vh[0], vh[1]);
                mmabf2(oa[2*t+1], pah, vh[2], vh[3]);
            }
        }
    }

    // --- close lane sums (deferred), normalize, write ctx packed ---
    l0r += __shfl_xor_sync(0xFFFFFFFFu, l0r, 1);
    l0r += __shfl_xor_sync(0xFFFFFFFFu, l0r, 2);
    l1r += __shfl_xor_sync(0xFFFFFFFFu, l1r, 1);
    l1r += __shfl_xor_sync(0xFFFFFFFFu, l1r, 2);
    float inv0 = 1.0f / l0r, inv1 = 1.0f / l1r;
    int sA = sq0 + wid*16 + g, sB = sA + 8;
    size_t baseA = ((size_t)(b*SS + sA)) * WPR + h*32;
    size_t baseB = ((size_t)(b*SS + sB)) * WPR + h*32;
    #pragma unroll
    for (int nch = 0; nch < 8; nch++) {
        uint32_t hw, lw;
        packbf2(oa[nch][0] * inv0, oa[nch][1] * inv0, hw, lw);
        g_Ch[baseA + nch*4 + c] = hw; g_Cl[baseA + nch*4 + c] = lw;
        packbf2(oa[nch][2] * inv1, oa[nch][3] * inv1, hw, lw);
        g_Ch[baseB + nch*4 + c] = hw; g_Cl[baseB + nch*4 + c] = lw;
    }
}

extern "C" void kernel_launch(void* const* d_in, const int* in_sizes, int n_in,
                              void* d_out, int out_size) {
    const float* hs   = (const float*)d_in[0];
    const float* mask = (const float*)d_in[1];
    const float* Wq   = (const float*)d_in[2];
    const float* bq   = (const float*)d_in[3];
    const float* Wk   = (const float*)d_in[4];
    const float* bk   = (const float*)d_in[5];
    const float* Wv   = (const float*)d_in[6];
    const float* bv   = (const float*)d_in[7];
    const float* Wo   = (const float*)d_in[8];
    const float* bo   = (const float*)d_in[9];
    const float* cosp = (const float*)d_in[10];
    const float* sinp = (const float*)d_in[11];
    float* out = (float*)d_out;

    cudaFuncSetAttribute(qkv_pk,   cudaFuncAttributeMaxDynamicSharedMemorySize, GEMM_SMEM);
    cudaFuncSetAttribute(o_pk,     cudaFuncAttributeMaxDynamicSharedMemorySize, GEMM_SMEM);
    cudaFuncSetAttribute(flash_pk, cudaFuncAttributeMaxDynamicSharedMemorySize, FLASH_SMEM);

    pack_x<<<768, 256>>>(hs);
    transpose_pack_w<<<dim3(24, 24, 4), dim3(32, 8)>>>(Wq, Wk, Wv, Wo);
    qkv_pk<<<dim3(12, 32, 3), 256, GEMM_SMEM>>>(bq, bk, bv, cosp, sinp);
    flash_pk<<<dim3(16, 24), 256, FLASH_SMEM>>>(mask);
    o_pk<<<dim3(12, 32), 256, GEMM_SMEM>>>(bo, out);
}

// round 14
// speedup vs baseline: 1.2263x; 1.1646x over previous
#include <cuda_runtime.h>
#include <cstdint>
#include <math.h>

#define BB 2
#define SS 2048
#define HH 768
#define NHH 12
#define HDD 64
#define WPR 384   // bf16-pair words per 768-row

// Packed bf16 hi/lo global scratch (allocation-free rule: __device__ globals)
__device__ uint32_t g_Xh[4096*WPR],  g_Xl[4096*WPR];
__device__ uint32_t g_WTh[4*HH*WPR], g_WTl[4*HH*WPR];   // [z][n][kpair]
__device__ uint32_t g_Qh[24*SS*32];                     // [bh][s][dpair] (pre-scaled 0.125*log2e), hi only
__device__ uint32_t g_Kh[24*SS*32];                     // [bh][s][dpair], hi only
__device__ uint32_t g_Vh[24*64*1024], g_Vl[24*64*1024]; // [bh][d][kvpair]
__device__ uint32_t g_Ch[4096*WPR],  g_Cl[4096*WPR];    // ctx packed

// ---------------------------------------------------------------------------
// Helpers
// ---------------------------------------------------------------------------
__device__ __forceinline__ uint32_t smem_u32(const void* p) {
    uint32_t a;
    asm("{ .reg .u64 t; cvta.to.shared.u64 t, %1; cvt.u32.u64 %0, t; }" : "=r"(a) : "l"(p));
    return a;
}

__device__ __forceinline__ void packbf2(float x0, float x1, uint32_t& hw, uint32_t& lw) {
    uint32_t h;
    asm("cvt.rn.bf16x2.f32 %0, %1, %2;" : "=r"(h) : "f"(x1), "f"(x0));
    float h0 = __uint_as_float(h << 16);
    float h1 = __uint_as_float(h & 0xFFFF0000u);
    asm("cvt.rn.bf16x2.f32 %0, %1, %2;" : "=r"(lw) : "f"(x1 - h1), "f"(x0 - h0));
    hw = h;
}

__device__ __forceinline__ uint32_t packbf2_hi(float x0, float x1) {
    uint32_t h;
    asm("cvt.rn.bf16x2.f32 %0, %1, %2;" : "=r"(h) : "f"(x1), "f"(x0));
    return h;
}

__device__ __forceinline__ void mmabf2(float d[4], const uint32_t a[4], uint32_t b0, uint32_t b1) {
    asm volatile(
        "mma.sync.aligned.m16n8k16.row.col.f32.bf16.bf16.f32 "
        "{%0,%1,%2,%3}, {%4,%5,%6,%7}, {%8,%9}, {%0,%1,%2,%3};"
        : "+f"(d[0]), "+f"(d[1]), "+f"(d[2]), "+f"(d[3])
        : "r"(a[0]), "r"(a[1]), "r"(a[2]), "r"(a[3]), "r"(b0), "r"(b1));
}

__device__ __forceinline__ void ldsm4(uint32_t r[4], uint32_t addr) {
    asm volatile("ldmatrix.sync.aligned.m8n8.x4.shared.b16 {%0,%1,%2,%3}, [%4];"
        : "=r"(r[0]), "=r"(r[1]), "=r"(r[2]), "=r"(r[3]) : "r"(addr));
}

__device__ __forceinline__ void cpa16(uint32_t saddr, const void* g) {
    asm volatile("cp.async.cg.shared.global [%0], [%1], 16;" :: "r"(saddr), "l"(g));
}
#define CPA_COMMIT() asm volatile("cp.async.commit_group;" ::: "memory")
#define CPA_WAIT1()  asm volatile("cp.async.wait_group 1;" ::: "memory")
#define CPA_WAIT0()  asm volatile("cp.async.wait_group 0;" ::: "memory")

// 2^x via MUFU. Scores pre-scaled by log2(e) upstream; masked ~-14427 -> 0.
__device__ __forceinline__ float fex2(float x) {
    float r;
    asm("ex2.approx.f32 %0, %1;" : "=f"(r) : "f"(x));
    return r;
}

// ---------------------------------------------------------------------------
// Prep kernels
// ---------------------------------------------------------------------------
__global__ void pack_x(const float* __restrict__ X) {
    int i = blockIdx.x * 256 + threadIdx.x;
    const int n = 4096 * WPR;
    for (int w = i; w < n; w += gridDim.x * 256) {
        float2 v = ((const float2*)X)[w];
        packbf2(v.x, v.y, g_Xh[w], g_Xl[w]);
    }
}

__global__ void transpose_pack_w(const float* __restrict__ W0, const float* __restrict__ W1,
                                 const float* __restrict__ W2, const float* __restrict__ W3) {
    __shared__ float t[32][33];
    int z = blockIdx.z;
    const float* W = z == 0 ? W0 : z == 1 ? W1 : z == 2 ? W2 : W3;
    uint32_t* WTh = g_WTh + (size_t)z * HH * WPR;
    uint32_t* WTl = g_WTl + (size_t)z * HH * WPR;
    int bx = blockIdx.x * 32, by = blockIdx.y * 32;
    int tx = threadIdx.x, ty = threadIdx.y;
    #pragma unroll
    for (int i = 0; i < 4; i++)
        t[ty + 8*i][tx] = W[(size_t)(by + ty + 8*i) * HH + bx + tx];
    __syncthreads();
    int li = ty * 32 + tx;
    #pragma unroll
    for (int it = 0; it < 2; it++) {
        int q = li + it * 256;
        int n_l = q >> 4, w = q & 15;
        uint32_t hw, lw;
        packbf2(t[2*w][n_l], t[2*w + 1][n_l], hw, lw);
        size_t addr = (size_t)(bx + n_l) * WPR + (by >> 1) + w;
        WTh[addr] = hw; WTl[addr] = lw;
    }
}

// ---------------------------------------------------------------------------
// Projection GEMM (2xBF16 m16n8k16), double-buffered, ldmatrix fragments.
// ---------------------------------------------------------------------------
#define W_BIAS 15360
#define W_COS  15424
#define W_SIN  15488
#define GEMM_SMEM (15552*4)

__device__ __forceinline__ void gemm_main(const uint32_t* __restrict__ Ahg,
                                          const uint32_t* __restrict__ Alg,
                                          const uint32_t* __restrict__ Bhg,
                                          const uint32_t* __restrict__ Blg,
                                          int m0, int n0, uint32_t* smw,
                                          float acc[2][4][4]) {
    const int tid = threadIdx.x;
    const int wid = tid >> 5, lane = tid & 31;
    const int wm = wid >> 1, wn = wid & 1;
    const int ar = tid >> 2, au = tid & 3;
    const int so0 = ar*20 + au*4, so1 = (ar + 64)*20 + au*4;
    const uint32_t sb = smem_u32(smw);

    const int l8 = (lane >> 3) & 1, l16 = lane >> 4, l7 = lane & 7;
    const int aoff0 = (wm*32 +        l8*8 + l7)*20 + l16*4;
    const int aoff1 = aoff0 + 16*20;
    const int boff0 = (wn*32 +        l16*8 + l7)*20 + l8*4;
    const int boff1 = boff0 + 16*20;

    const uint32_t* pA0h = Ahg + (size_t)(m0 + ar) * WPR + au*4;
    const uint32_t* pA1h = pA0h + (size_t)64 * WPR;
    const uint32_t* pA0l = Alg + (size_t)(m0 + ar) * WPR + au*4;
    const uint32_t* pA1l = pA0l + (size_t)64 * WPR;
    const uint32_t* pBh  = Bhg + (size_t)(n0 + ar) * WPR + au*4;
    const uint32_t* pBl  = Blg + (size_t)(n0 + ar) * WPR + au*4;

    uint4 a0h = *(const uint4*)pA0h, a1h = *(const uint4*)pA1h;
    uint4 a0l = *(const uint4*)pA0l, a1l = *(const uint4*)pA1l;
    uint4 b0h = *(const uint4*)pBh,  b0l = *(const uint4*)pBl;
    *(uint4*)(smw + so0)         = a0h; *(uint4*)(smw + so1)         = a1h;
    *(uint4*)(smw + 2560 + so0)  = a0l; *(uint4*)(smw + 2560 + so1)  = a1l;
    *(uint4*)(smw + 10240 + so0) = b0h;
    *(uint4*)(smw + 11520 + so0) = b0l;

    for (int kb = 0; kb < 24; kb++) {
        const int cur = kb & 1;
        if (kb < 23) {
            int ko = (kb + 1) * 16;
            a0h = *(const uint4*)(pA0h + ko); a1h = *(const uint4*)(pA1h + ko);
            a0l = *(const uint4*)(pA0l + ko); a1l = *(const uint4*)(pA1l + ko);
            b0h = *(const uint4*)(pBh + ko);  b0l = *(const uint4*)(pBl + ko);
        }
        __syncthreads();
        const int AH = cur*5120, AL = AH + 2560;
        const int BH = 10240 + cur*2560, BL = BH + 1280;
        #pragma unroll
        for (int ks = 0; ks < 2; ks++) {
            int kk = ks * 8;
            uint32_t ah0[4], ah1[4], al0[4], al1[4];
            uint32_t bh0[4], bh1[4], bl0[4], bl1[4];
            ldsm4(ah0, sb + (AH + aoff0 + kk)*4);
            ldsm4(ah1, sb + (AH + aoff1 + kk)*4);
            ldsm4(al0, sb + (AL + aoff0 + kk)*4);
            ldsm4(al1, sb + (AL + aoff1 + kk)*4);
            ldsm4(bh0, sb + (BH + boff0 + kk)*4);
            ldsm4(bh1, sb + (BH + boff1 + kk)*4);
            ldsm4(bl0, sb + (BL + boff0 + kk)*4);
            ldsm4(bl1, sb + (BL + boff1 + kk)*4);
            mmabf2(acc[0][0], al0, bh0[0], bh0[1]); mmabf2(acc[0][1], al0, bh0[2], bh0[3]);
            mmabf2(acc[0][2], al0, bh1[0], bh1[1]); mmabf2(acc[0][3], al0, bh1[2], bh1[3]);
            mmabf2(acc[1][0], al1, bh0[0], bh0[1]); mmabf2(acc[1][1], al1, bh0[2], bh0[3]);
            mmabf2(acc[1][2], al1, bh1[0], bh1[1]); mmabf2(acc[1][3], al1, bh1[2], bh1[3]);
            mmabf2(acc[0][0], ah0, bl0[0], bl0[1]); mmabf2(acc[0][1], ah0, bl0[2], bl0[3]);
            mmabf2(acc[0][2], ah0, bl1[0], bl1[1]); mmabf2(acc[0][3], ah0, bl1[2], bl1[3]);
            mmabf2(acc[1][0], ah1, bl0[0], bl0[1]); mmabf2(acc[1][1], ah1, bl0[2], bl0[3]);
            mmabf2(acc[1][2], ah1, bl1[0], bl1[1]); mmabf2(acc[1][3], ah1, bl1[2], bl1[3]);
            mmabf2(acc[0][0], ah0, bh0[0], bh0[1]); mmabf2(acc[0][1], ah0, bh0[2], bh0[3]);
            mmabf2(acc[0][2], ah0, bh1[0], bh1[1]); mmabf2(acc[0][3], ah0, bh1[2], bh1[3]);
            mmabf2(acc[1][0], ah1, bh0[0], bh0[1]); mmabf2(acc[1][1], ah1, bh0[2], bh0[3]);
            mmabf2(acc[1][2], ah1, bh1[0], bh1[1]); mmabf2(acc[1][3], ah1, bh1[2], bh1[3]);
        }
        if (kb < 23) {
            const int nxt = (1 - cur) * 5120;
            const int nxb = 10240 + (1 - cur) * 2560;
            *(uint4*)(smw + nxt + so0)        = a0h; *(uint4*)(smw + nxt + so1)        = a1h;
            *(uint4*)(smw + nxt + 2560 + so0) = a0l; *(uint4*)(smw + nxt + 2560 + so1) = a1l;
            *(uint4*)(smw + nxb + so0)        = b0h;
            *(uint4*)(smw + nxb + 1280 + so0) = b0l;
        }
    }
    __syncthreads();
}

__device__ __forceinline__ void stage_acc(uint32_t* smw, float acc[2][4][4]) {
    const int tid = threadIdx.x;
    const int wid = tid >> 5, lane = tid & 31, g = lane >> 2, c = lane & 3;
    const int wm = wid >> 1, wn = wid & 1;
    float* Sg = (float*)smw;
    #pragma unroll
    for (int mt = 0; mt < 2; mt++) {
        int r0 = wm*32 + mt*16 + g;
        #pragma unroll
        for (int nt = 0; nt < 4; nt++) {
            int col = wn*32 + nt*8 + 2*c;
            *(float2*)&Sg[r0*66 + col]       = make_float2(acc[mt][nt][0], acc[mt][nt][1]);
            *(float2*)&Sg[(r0 + 8)*66 + col] = make_float2(acc[mt][nt][2], acc[mt][nt][3]);
        }
    }
    __syncthreads();
}

// ---------------------------------------------------------------------------
// QKV projection + bias + RoPE (head-indexed, faithful), packed outputs.
// Q pre-scaled by 0.125*log2(e); Q/K stored hi-only (flash QK is 1-pass).
// ---------------------------------------------------------------------------
__global__ __launch_bounds__(256, 2)
void qkv_pk(const float* __restrict__ bq, const float* __restrict__ bk,
            const float* __restrict__ bv,
            const float* __restrict__ cosp, const float* __restrict__ sinp) {
    extern __shared__ uint32_t smw[];
    int tid = threadIdx.x;
    int z = blockIdx.z;
    int m0 = blockIdx.y * 128, n0 = blockIdx.x * 64;
    const float* bias = z == 0 ? bq : z == 1 ? bk : bv;

    if (tid < 64) {
        ((float*)(smw + W_BIAS))[tid] = bias[n0 + tid];
        ((float*)(smw + W_COS ))[tid] = cosp[n0 + tid];
        ((float*)(smw + W_SIN ))[tid] = sinp[n0 + tid];
    }
    float acc[2][4][4] = {};
    size_t zo = (size_t)z * HH * WPR;
    gemm_main(g_Xh, g_Xl, g_WTh + zo, g_WTl + zo, m0, n0, smw, acc);
    stage_acc(smw, acc);

    float* Sg = (float*)smw;
    const float* sBias = (const float*)(smw + W_BIAS);
    const float* sCos  = (const float*)(smw + W_COS);
    const float* sSin  = (const float*)(smw + W_SIN);
    int m = tid >> 1;
    int half = (tid & 1) * 32;
    int mg = m0 + m;
    int bbt = mg >> 11, s = mg & 2047;
    int h = blockIdx.x;
    int bh = bbt * NHH + h;

    float o[32];
    if (z < 2) {
        // 0.125 * log2(e): folds softmax's exp->ex2 conversion into Q.
        float qsc = (z == 0) ? 0.18033688011112042f : 1.0f;
        #pragma unroll
        for (int i = 0; i < 32; i++) {
            int cg = half + i;
            float v = Sg[m*66 + cg] + sBias[cg];
            int pc = (cg < 32) ? (2*cg + 1) : (2*(cg - 32));
            float pv = Sg[m*66 + pc] + sBias[pc];
            float sgn = (cg < 32) ? -1.0f : 1.0f;
            o[i] = (v * sCos[cg] + sgn * pv * sSin[cg]) * qsc;
        }
        uint32_t* Dh = (z == 0 ? g_Qh : g_Kh) + ((size_t)bh * SS + s) * 32 + (tid & 1) * 16;
        #pragma unroll
        for (int j = 0; j < 16; j++)
            Dh[j] = packbf2_hi(o[2*j], o[2*j + 1]);
    } else {
        #pragma unroll
        for (int i = 0; i < 32; i++)
            o[i] = Sg[m*66 + half + i] + sBias[half + i];
        size_t base = (size_t)bh * 64 * 1024 + ((m0 & 2047) >> 1) + (tid >> 2);
        #pragma unroll
        for (int i = 0; i < 32; i++) {
            float pv = __shfl_down_sync(0xFFFFFFFFu, o[i], 2);
            if (!(tid & 2)) {
                uint32_t hw, lw;
                packbf2(o[i], pv, hw, lw);
                g_Vh[base + (size_t)(half + i) * 1024] = hw;
                g_Vl[base + (size_t)(half + i) * 1024] = lw;
            }
        }
    }
}

__global__ __launch_bounds__(256, 2)
void o_pk(const float* __restrict__ bo, float* __restrict__ out) {
    extern __shared__ uint32_t smw[];
    int tid = threadIdx.x;
    int m0 = blockIdx.y * 128, n0 = blockIdx.x * 64;
    if (tid < 64) ((float*)(smw + W_BIAS))[tid] = bo[n0 + tid];

    float acc[2][4][4] = {};
    size_t zo = (size_t)3 * HH * WPR;
    gemm_main(g_Ch, g_Cl, g_WTh + zo, g_WTl + zo, m0, n0, smw, acc);
    stage_acc(smw, acc);

    float* Sg = (float*)smw;
    const float* sBias = (const float*)(smw + W_BIAS);
    int m = tid >> 1;
    int half = (tid & 1) * 32;
    float* dst = out + (size_t)(m0 + m) * HH + n0 + half;
    #pragma unroll
    for (int i4 = 0; i4 < 8; i4++) {
        float4 v;
        v.x = Sg[m*66 + half + i4*4 + 0] + sBias[half + i4*4 + 0];
        v.y = Sg[m*66 + half + i4*4 + 1] + sBias[half + i4*4 + 1];
        v.z = Sg[m*66 + half + i4*4 + 2] + sBias[half + i4*4 + 2];
        v.w = Sg[m*66 + half + i4*4 + 3] + sBias[half + i4*4 + 3];
        *(float4*)(dst + i4*4) = v;
    }
}

// ---------------------------------------------------------------------------
// Flash attention v7b: single-pass bf16 QK^T, 3-pass PV, ex2 softmax,
// 2 CTAs/SM, Q persistent (hi only; FIXED staging: 4 iterations = all 128
// rows), double-buffered cp.async K(hi)/V(hi+lo).
// smem words: buf q at q*6912 {KH+0, VH+2304, VL+4608}; QH 13824 (4608);
// mask 18432 + q*64. Total 18560 w = 74.24 KB.
// ---------------------------------------------------------------------------
#define FV_BUF(q) ((q)*6912)
#define FV_QH 13824
#define FV_MSB(q) (18432 + (q)*64)
#define FLASH_SMEM (18560*4)

__global__ __launch_bounds__(256, 2)
void flash_pk(const float* __restrict__ mask) {
    extern __shared__ uint32_t smw[];
    const uint32_t sb = smem_u32(smw);
    int bh = blockIdx.y;
    int b = bh / NHH, h = bh % NHH;
    int sq0 = blockIdx.x * 128;
    const float* mkg = mask + (size_t)b * SS;
    int tid = threadIdx.x;
    int wid = tid >> 5, lane = tid & 31, g = lane >> 2, c = lane & 3;
    const int l8 = (lane >> 3) & 1, l16 = lane >> 4, l7 = lane & 7;

    const uint32_t* Khg0 = g_Kh + (size_t)bh * SS * 32;
    const uint32_t* Vhg0 = g_Vh + (size_t)bh * 64 * 1024;
    const uint32_t* Vlg0 = g_Vl + (size_t)bh * 64 * 1024;
    const int cr = tid >> 3, cu = tid & 7;   // staging row/quad

    const int qoff = (wid*16 + l8*8 + l7)*36 + l16*4;
    int koff[4];
    #pragma unroll
    for (int t = 0; t < 4; t++)
        koff[t] = (t*16 + l16*8 + l7)*36 + l8*4;   // same formula for K and V

    // prologue: issue K/V tile 0 into buf0 (async)
    {
        uint32_t kb = FV_BUF(0);
        #pragma unroll
        for (int it = 0; it < 2; it++) {
            int r = cr + it*32;
            uint32_t wo = (r*36 + cu*4)*4;
            cpa16(sb + kb*4          + wo, Khg0 + r*32 + cu*4);
            cpa16(sb + (kb + 2304)*4 + wo, Vhg0 + (size_t)r*1024 + cu*4);
            cpa16(sb + (kb + 4608)*4 + wo, Vlg0 + (size_t)r*1024 + cu*4);
        }
        if (tid < 16) cpa16(sb + (FV_MSB(0) + tid*4)*4, mkg + tid*4);
        CPA_COMMIT();
    }

    // stage Q (128 rows, hi only) into persistent smem region.
    // 128 rows x 8 uint4/row = 1024 transfers -> FOUR iterations of 256 thr.
    {
        const uint32_t* Qhg = g_Qh + ((size_t)bh * SS + sq0) * 32;
        #pragma unroll
        for (int it = 0; it < 4; it++) {
            int idx = tid + it * 256;
            int r = idx >> 3, u = idx & 7;
            *(uint4*)(smw + FV_QH + r*36 + u*4) = *(const uint4*)(Qhg + r*32 + u*4);
        }
    }

    float oa[8][4] = {};
    float l0r = 0.0f, l1r = 0.0f;   // per-lane partial row sums

    for (int jt = 0; jt < 32; jt++) {
        const int cur = jt & 1;
        __syncthreads();   // compute on buf[1-cur] (jt-1) done; Q stores visible at jt=0
        if (jt < 31) {
            int jn = jt + 1;
            uint32_t kb = FV_BUF(1 - cur);
            const uint32_t* Khg = Khg0 + (size_t)jn*64*32 + cr*32 + cu*4;
            const uint32_t* Vhg = Vhg0 + jn*32 + (size_t)cr*1024 + cu*4;
            const uint32_t* Vlg = Vlg0 + jn*32 + (size_t)cr*1024 + cu*4;
            #pragma unroll
            for (int it = 0; it < 2; it++) {
                int r = cr + it*32;
                uint32_t wo = (r*36 + cu*4)*4;
                cpa16(sb + kb*4          + wo, Khg + it*32*32);
                cpa16(sb + (kb + 2304)*4 + wo, Vhg + (size_t)it*32*1024);
                cpa16(sb + (kb + 4608)*4 + wo, Vlg + (size_t)it*32*1024);
            }
            if (tid < 16) cpa16(sb + (FV_MSB(1 - cur) + tid*4)*4, mkg + jn*64 + tid*4);
        }
        CPA_COMMIT();
        if (jt < 31) CPA_WAIT1(); else CPA_WAIT0();
        __syncthreads();   // tile jt data visible to all threads

        const uint32_t KHb = FV_BUF(cur);
        const uint32_t VHb = KHb + 2304, VLb = KHb + 4608;
        const float* msf = (const float*)(smw + FV_MSB(cur));

        // --- S = Q @ K^T, single-pass bf16 (scores in log2 domain) ---
        float sv[8][4] = {};
        #pragma unroll
        for (int ks = 0; ks < 4; ks++) {
            int kk = ks * 8;
            uint32_t qh[4];
            ldsm4(qh, sb + (FV_QH + qoff + kk)*4);
            #pragma unroll
            for (int t = 0; t < 4; t++) {
                uint32_t bhf[4];
                ldsm4(bhf, sb + (KHb + koff[t] + kk)*4);
                mmabf2(sv[2*t],   qh, bhf[0], bhf[1]);
                mmabf2(sv[2*t+1], qh, bhf[2], bhf[3]);
            }
        }

        // --- softmax: p = ex2(s + mask_log2), accumulate lane sums ---
        #pragma unroll
        for (int nt = 0; nt < 8; nt++) {
            int col = nt*8 + 2*c;
            float ma = fmaf(msf[col],     14426.950408889634f, -14426.950408889634f);
            float mb = fmaf(msf[col + 1], 14426.950408889634f, -14426.950408889634f);
            sv[nt][0] = fex2(sv[nt][0] + ma); l0r += sv[nt][0];
            sv[nt][1] = fex2(sv[nt][1] + mb); l0r += sv[nt][1];
            sv[nt][2] = fex2(sv[nt][2] + ma); l1r += sv[nt][2];
            sv[nt][3] = fex2(sv[nt][3] + mb); l1r += sv[nt][3];
        }

        // --- O += P @ V (3-pass); pack P per-ks inside the loop ---
        #pragma unroll
        for (int ks = 0; ks < 4; ks++) {
            uint32_t pah[4], pal[4];
            packbf2(sv[2*ks][0],   sv[2*ks][1],   pah[0], pal[0]);
            packbf2(sv[2*ks][2],   sv[2*ks][3],   pah[1], pal[1]);
            packbf2(sv[2*ks+1][0], sv[2*ks+1][1], pah[2], pal[2]);
            packbf2(sv[2*ks+1][2], sv[2*ks+1][3], pah[3], pal[3]);
            int kk = ks * 8;
            #pragma unroll
            for (int t = 0; t < 4; t++) {
                uint32_t vh[4], vl[4];
                ldsm4(vh, sb + (VHb + koff[t] + kk)*4);
                ldsm4(vl, sb + (VLb + koff[t] + kk)*4);
                mmabf2(oa[2*t],   pal, vh[0], vh[1]);
                mmabf2(oa[2*t+1], pal, vh[2], vh[3]);
                mmabf2(oa[2*t],   pah, vl[0], vl[1]);
                mmabf2(oa[2*t+1], pah, vl[2], vl[3]);
                mmabf2(oa[2*t],   pah, vh[0], vh[1]);
                mmabf2(oa[2*t+1], pah, vh[2], vh[3]);
            }
        }
    }

    // --- close lane sums (deferred), normalize, write ctx packed ---
    l0r += __shfl_xor_sync(0xFFFFFFFFu, l0r, 1);
    l0r += __shfl_xor_sync(0xFFFFFFFFu, l0r, 2);
    l1r += __shfl_xor_sync(0xFFFFFFFFu, l1r, 1);
    l1r += __shfl_xor_sync(0xFFFFFFFFu, l1r, 2);
    float inv0 = 1.0f / l0r, inv1 = 1.0f / l1r;
    int sA = sq0 + wid*16 + g, sB = sA + 8;
    size_t baseA = ((size_t)(b*SS + sA)) * WPR + h*32;
    size_t baseB = ((size_t)(b*SS + sB)) * WPR + h*32;
    #pragma unroll
    for (int nch = 0; nch < 8; nch++) {
        uint32_t hw, lw;
        packbf2(oa[nch][0] * inv0, oa[nch][1] * inv0, hw, lw);
        g_Ch[baseA + nch*4 + c] = hw; g_Cl[baseA + nch*4 + c] = lw;
        packbf2(oa[nch][2] * inv1, oa[nch][3] * inv1, hw, lw);
        g_Ch[baseB + nch*4 + c] = hw; g_Cl[baseB + nch*4 + c] = lw;
    }
}

extern "C" void kernel_launch(void* const* d_in, const int* in_sizes, int n_in,
                              void* d_out, int out_size) {
    const float* hs   = (const float*)d_in[0];
    const float* mask = (const float*)d_in[1];
    const float* Wq   = (const float*)d_in[2];
    const float* bq   = (const float*)d_in[3];
    const float* Wk   = (const float*)d_in[4];
    const float* bk   = (const float*)d_in[5];
    const float* Wv   = (const float*)d_in[6];
    const float* bv   = (const float*)d_in[7];
    const float* Wo   = (const float*)d_in[8];
    const float* bo   = (const float*)d_in[9];
    const float* cosp = (const float*)d_in[10];
    const float* sinp = (const float*)d_in[11];
    float* out = (float*)d_out;

    cudaFuncSetAttribute(qkv_pk,   cudaFuncAttributeMaxDynamicSharedMemorySize, GEMM_SMEM);
    cudaFuncSetAttribute(o_pk,     cudaFuncAttributeMaxDynamicSharedMemorySize, GEMM_SMEM);
    cudaFuncSetAttribute(flash_pk, cudaFuncAttributeMaxDynamicSharedMemorySize, FLASH_SMEM);

    pack_x<<<768, 256>>>(hs);
    transpose_pack_w<<<dim3(24, 24, 4), dim3(32, 8)>>>(Wq, Wk, Wv, Wo);
    qkv_pk<<<dim3(12, 32, 3), 256, GEMM_SMEM>>>(bq, bk, bv, cosp, sinp);
    flash_pk<<<dim3(16, 24), 256, FLASH_SMEM>>>(mask);
    o_pk<<<dim3(12, 32), 256, GEMM_SMEM>>>(bo, out);
}

// round 15
// speedup vs baseline: 1.2316x; 1.0043x over previous
#include <cuda_runtime.h>
#include <cstdint>
#include <math.h>

#define BB 2
#define SS 2048
#define HH 768
#define NHH 12
#define HDD 64
#define WPR 384   // bf16-pair words per 768-row

// Packed global scratch (allocation-free rule: __device__ globals)
__device__ uint32_t g_Xh[4096*WPR],  g_Xl[4096*WPR];
__device__ uint32_t g_WTh[4*HH*WPR], g_WTl[4*HH*WPR];   // [z][n][kpair]
__device__ uint32_t g_Qh[24*SS*32];                     // [bh][s][dpair] fp16x2 (pre-scaled 0.125*log2e)
__device__ uint32_t g_Kh[24*SS*32];                     // [bh][s][dpair] fp16x2
__device__ uint32_t g_Vh[24*64*1024], g_Vl[24*64*1024]; // [bh][d][kvpair] bf16 hi/lo
__device__ uint32_t g_Ch[4096*WPR],  g_Cl[4096*WPR];    // ctx packed bf16 hi/lo

// ---------------------------------------------------------------------------
// Helpers
// ---------------------------------------------------------------------------
__device__ __forceinline__ uint32_t smem_u32(const void* p) {
    uint32_t a;
    asm("{ .reg .u64 t; cvta.to.shared.u64 t, %1; cvt.u32.u64 %0, t; }" : "=r"(a) : "l"(p));
    return a;
}

__device__ __forceinline__ void packbf2(float x0, float x1, uint32_t& hw, uint32_t& lw) {
    uint32_t h;
    asm("cvt.rn.bf16x2.f32 %0, %1, %2;" : "=r"(h) : "f"(x1), "f"(x0));
    float h0 = __uint_as_float(h << 16);
    float h1 = __uint_as_float(h & 0xFFFF0000u);
    asm("cvt.rn.bf16x2.f32 %0, %1, %2;" : "=r"(lw) : "f"(x1 - h1), "f"(x0 - h0));
    hw = h;
}

__device__ __forceinline__ uint32_t packfp2_hi(float x0, float x1) {
    uint32_t h;
    asm("cvt.rn.f16x2.f32 %0, %1, %2;" : "=r"(h) : "f"(x1), "f"(x0));
    return h;
}

__device__ __forceinline__ void mmabf2(float d[4], const uint32_t a[4], uint32_t b0, uint32_t b1) {
    asm volatile(
        "mma.sync.aligned.m16n8k16.row.col.f32.bf16.bf16.f32 "
        "{%0,%1,%2,%3}, {%4,%5,%6,%7}, {%8,%9}, {%0,%1,%2,%3};"
        : "+f"(d[0]), "+f"(d[1]), "+f"(d[2]), "+f"(d[3])
        : "r"(a[0]), "r"(a[1]), "r"(a[2]), "r"(a[3]), "r"(b0), "r"(b1));
}

__device__ __forceinline__ void mmafp2(float d[4], const uint32_t a[4], uint32_t b0, uint32_t b1) {
    asm volatile(
        "mma.sync.aligned.m16n8k16.row.col.f32.f16.f16.f32 "
        "{%0,%1,%2,%3}, {%4,%5,%6,%7}, {%8,%9}, {%0,%1,%2,%3};"
        : "+f"(d[0]), "+f"(d[1]), "+f"(d[2]), "+f"(d[3])
        : "r"(a[0]), "r"(a[1]), "r"(a[2]), "r"(a[3]), "r"(b0), "r"(b1));
}

__device__ __forceinline__ void ldsm4(uint32_t r[4], uint32_t addr) {
    asm volatile("ldmatrix.sync.aligned.m8n8.x4.shared.b16 {%0,%1,%2,%3}, [%4];"
        : "=r"(r[0]), "=r"(r[1]), "=r"(r[2]), "=r"(r[3]) : "r"(addr));
}

__device__ __forceinline__ void cpa16(uint32_t saddr, const void* g) {
    asm volatile("cp.async.cg.shared.global [%0], [%1], 16;" :: "r"(saddr), "l"(g));
}
#define CPA_COMMIT() asm volatile("cp.async.commit_group;" ::: "memory")
#define CPA_WAIT1()  asm volatile("cp.async.wait_group 1;" ::: "memory")
#define CPA_WAIT0()  asm volatile("cp.async.wait_group 0;" ::: "memory")

// 2^x via MUFU. Scores pre-scaled by log2(e) upstream; masked ~-14427 -> 0.
__device__ __forceinline__ float fex2(float x) {
    float r;
    asm("ex2.approx.f32 %0, %1;" : "=f"(r) : "f"(x));
    return r;
}

// ---------------------------------------------------------------------------
// Prep kernels
// ---------------------------------------------------------------------------
__global__ void pack_x(const float* __restrict__ X) {
    int i = blockIdx.x * 256 + threadIdx.x;
    const int n = 4096 * WPR;
    for (int w = i; w < n; w += gridDim.x * 256) {
        float2 v = ((const float2*)X)[w];
        packbf2(v.x, v.y, g_Xh[w], g_Xl[w]);
    }
}

__global__ void transpose_pack_w(const float* __restrict__ W0, const float* __restrict__ W1,
                                 const float* __restrict__ W2, const float* __restrict__ W3) {
    __shared__ float t[32][33];
    int z = blockIdx.z;
    const float* W = z == 0 ? W0 : z == 1 ? W1 : z == 2 ? W2 : W3;
    uint32_t* WTh = g_WTh + (size_t)z * HH * WPR;
    uint32_t* WTl = g_WTl + (size_t)z * HH * WPR;
    int bx = blockIdx.x * 32, by = blockIdx.y * 32;
    int tx = threadIdx.x, ty = threadIdx.y;
    #pragma unroll
    for (int i = 0; i < 4; i++)
        t[ty + 8*i][tx] = W[(size_t)(by + ty + 8*i) * HH + bx + tx];
    __syncthreads();
    int li = ty * 32 + tx;
    #pragma unroll
    for (int it = 0; it < 2; it++) {
        int q = li + it * 256;
        int n_l = q >> 4, w = q & 15;
        uint32_t hw, lw;
        packbf2(t[2*w][n_l], t[2*w + 1][n_l], hw, lw);
        size_t addr = (size_t)(bx + n_l) * WPR + (by >> 1) + w;
        WTh[addr] = hw; WTl[addr] = lw;
    }
}

// ---------------------------------------------------------------------------
// Projection GEMM (2xBF16 m16n8k16), cp.async double-buffered (LDG latency
// hidden by construction — the register-staged variant exposed 200-400 cyc
// per chunk at the tail STS). Numerics identical to R14 (same mma order).
// smem words: A buf0 hi 0 / lo 2560; A buf1 5120/7680; B buf0 10240/11520;
// B buf1 12800/14080; bias 15360, cos 15424, sin 15488.
// ---------------------------------------------------------------------------
#define W_BIAS 15360
#define W_COS  15424
#define W_SIN  15488
#define GEMM_SMEM (15552*4)

__device__ __forceinline__ void gemm_stage(const uint32_t* __restrict__ Ahg,
                                           const uint32_t* __restrict__ Alg,
                                           const uint32_t* __restrict__ Bhg,
                                           const uint32_t* __restrict__ Blg,
                                           int m0, int n0, int k0w, int buf,
                                           uint32_t sb, int tid) {
    const int r4 = tid >> 2, u4 = tid & 3;         // r4 0..63, u4 0..3
    const uint32_t ab = buf*5120, bb = 10240 + buf*2560;
    #pragma unroll
    for (int it = 0; it < 2; it++) {
        int r = r4 + it*64;
        uint32_t wo = (uint32_t)(r*20 + u4*4);
        cpa16(sb + (ab + wo)*4,        Ahg + (size_t)(m0 + r)*WPR + k0w + u4*4);
        cpa16(sb + (ab + 2560 + wo)*4, Alg + (size_t)(m0 + r)*WPR + k0w + u4*4);
    }
    {
        uint32_t wo = (uint32_t)(r4*20 + u4*4);
        cpa16(sb + (bb + wo)*4,        Bhg + (size_t)(n0 + r4)*WPR + k0w + u4*4);
        cpa16(sb + (bb + 1280 + wo)*4, Blg + (size_t)(n0 + r4)*WPR + k0w + u4*4);
    }
}

__device__ __forceinline__ void gemm_main(const uint32_t* __restrict__ Ahg,
                                          const uint32_t* __restrict__ Alg,
                                          const uint32_t* __restrict__ Bhg,
                                          const uint32_t* __restrict__ Blg,
                                          int m0, int n0, uint32_t* smw,
                                          float acc[2][4][4]) {
    const int tid = threadIdx.x;
    const int wid = tid >> 5, lane = tid & 31;
    const int wm = wid >> 1, wn = wid & 1;
    const uint32_t sb = smem_u32(smw);

    const int l8 = (lane >> 3) & 1, l16 = lane >> 4, l7 = lane & 7;
    const int aoff0 = (wm*32 +        l8*8 + l7)*20 + l16*4;
    const int aoff1 = aoff0 + 16*20;
    const int boff0 = (wn*32 +        l16*8 + l7)*20 + l8*4;
    const int boff1 = boff0 + 16*20;

    gemm_stage(Ahg, Alg, Bhg, Blg, m0, n0, 0, 0, sb, tid);
    CPA_COMMIT();

    for (int kb = 0; kb < 24; kb++) {
        const int cur = kb & 1;
        __syncthreads();   // mma on buf[1-cur] (chunk kb-1) done before overwrite
        if (kb < 23)
            gemm_stage(Ahg, Alg, Bhg, Blg, m0, n0, (kb + 1)*16, 1 - cur, sb, tid);
        CPA_COMMIT();
        if (kb < 23) CPA_WAIT1(); else CPA_WAIT0();
        __syncthreads();   // chunk kb visible

        const int AH = cur*5120, AL = AH + 2560;
        const int BH = 10240 + cur*2560, BL = BH + 1280;
        #pragma unroll
        for (int ks = 0; ks < 2; ks++) {
            int kk = ks * 8;
            uint32_t ah0[4], ah1[4], al0[4], al1[4];
            uint32_t bh0[4], bh1[4], bl0[4], bl1[4];
            ldsm4(ah0, sb + (AH + aoff0 + kk)*4);
            ldsm4(ah1, sb + (AH + aoff1 + kk)*4);
            ldsm4(al0, sb + (AL + aoff0 + kk)*4);
            ldsm4(al1, sb + (AL + aoff1 + kk)*4);
            ldsm4(bh0, sb + (BH + boff0 + kk)*4);
            ldsm4(bh1, sb + (BH + boff1 + kk)*4);
            ldsm4(bl0, sb + (BL + boff0 + kk)*4);
            ldsm4(bl1, sb + (BL + boff1 + kk)*4);
            mmabf2(acc[0][0], al0, bh0[0], bh0[1]); mmabf2(acc[0][1], al0, bh0[2], bh0[3]);
            mmabf2(acc[0][2], al0, bh1[0], bh1[1]); mmabf2(acc[0][3], al0, bh1[2], bh1[3]);
            mmabf2(acc[1][0], al1, bh0[0], bh0[1]); mmabf2(acc[1][1], al1, bh0[2], bh0[3]);
            mmabf2(acc[1][2], al1, bh1[0], bh1[1]); mmabf2(acc[1][3], al1, bh1[2], bh1[3]);
            mmabf2(acc[0][0], ah0, bl0[0], bl0[1]); mmabf2(acc[0][1], ah0, bl0[2], bl0[3]);
            mmabf2(acc[0][2], ah0, bl1[0], bl1[1]); mmabf2(acc[0][3], ah0, bl1[2], bl1[3]);
            mmabf2(acc[1][0], ah1, bl0[0], bl0[1]); mmabf2(acc[1][1], ah1, bl0[2], bl0[3]);
            mmabf2(acc[1][2], ah1, bl1[0], bl1[1]); mmabf2(acc[1][3], ah1, bl1[2], bl1[3]);
            mmabf2(acc[0][0], ah0, bh0[0], bh0[1]); mmabf2(acc[0][1], ah0, bh0[2], bh0[3]);
            mmabf2(acc[0][2], ah0, bh1[0], bh1[1]); mmabf2(acc[0][3], ah0, bh1[2], bh1[3]);
            mmabf2(acc[1][0], ah1, bh0[0], bh0[1]); mmabf2(acc[1][1], ah1, bh0[2], bh0[3]);
            mmabf2(acc[1][2], ah1, bh1[0], bh1[1]); mmabf2(acc[1][3], ah1, bh1[2], bh1[3]);
        }
    }
    __syncthreads();
}

__device__ __forceinline__ void stage_acc(uint32_t* smw, float acc[2][4][4]) {
    const int tid = threadIdx.x;
    const int wid = tid >> 5, lane = tid & 31, g = lane >> 2, c = lane & 3;
    const int wm = wid >> 1, wn = wid & 1;
    float* Sg = (float*)smw;
    #pragma unroll
    for (int mt = 0; mt < 2; mt++) {
        int r0 = wm*32 + mt*16 + g;
        #pragma unroll
        for (int nt = 0; nt < 4; nt++) {
            int col = wn*32 + nt*8 + 2*c;
            *(float2*)&Sg[r0*66 + col]       = make_float2(acc[mt][nt][0], acc[mt][nt][1]);
            *(float2*)&Sg[(r0 + 8)*66 + col] = make_float2(acc[mt][nt][2], acc[mt][nt][3]);
        }
    }
    __syncthreads();
}

// ---------------------------------------------------------------------------
// QKV projection + bias + RoPE (head-indexed, faithful), packed outputs.
// Q pre-scaled by 0.125*log2(e); Q/K stored as fp16x2 (flash QK is 1-pass
// fp16 — 8x less quantization noise than bf16).
// ---------------------------------------------------------------------------
__global__ __launch_bounds__(256, 2)
void qkv_pk(const float* __restrict__ bq, const float* __restrict__ bk,
            const float* __restrict__ bv,
            const float* __restrict__ cosp, const float* __restrict__ sinp) {
    extern __shared__ uint32_t smw[];
    int tid = threadIdx.x;
    int z = blockIdx.z;
    int m0 = blockIdx.y * 128, n0 = blockIdx.x * 64;
    const float* bias = z == 0 ? bq : z == 1 ? bk : bv;

    if (tid < 64) {
        ((float*)(smw + W_BIAS))[tid] = bias[n0 + tid];
        ((float*)(smw + W_COS ))[tid] = cosp[n0 + tid];
        ((float*)(smw + W_SIN ))[tid] = sinp[n0 + tid];
    }
    __syncthreads();   // bias region stable before cp.async pipeline starts
    float acc[2][4][4] = {};
    size_t zo = (size_t)z * HH * WPR;
    gemm_main(g_Xh, g_Xl, g_WTh + zo, g_WTl + zo, m0, n0, smw, acc);
    stage_acc(smw, acc);

    float* Sg = (float*)smw;
    const float* sBias = (const float*)(smw + W_BIAS);
    const float* sCos  = (const float*)(smw + W_COS);
    const float* sSin  = (const float*)(smw + W_SIN);
    int m = tid >> 1;
    int half = (tid & 1) * 32;
    int mg = m0 + m;
    int bbt = mg >> 11, s = mg & 2047;
    int h = blockIdx.x;
    int bh = bbt * NHH + h;

    float o[32];
    if (z < 2) {
        // 0.125 * log2(e): folds softmax's exp->ex2 conversion into Q.
        float qsc = (z == 0) ? 0.18033688011112042f : 1.0f;
        #pragma unroll
        for (int i = 0; i < 32; i++) {
            int cg = half + i;
            float v = Sg[m*66 + cg] + sBias[cg];
            int pc = (cg < 32) ? (2*cg + 1) : (2*(cg - 32));
            float pv = Sg[m*66 + pc] + sBias[pc];
            float sgn = (cg < 32) ? -1.0f : 1.0f;
            o[i] = (v * sCos[cg] + sgn * pv * sSin[cg]) * qsc;
        }
        uint32_t* Dh = (z == 0 ? g_Qh : g_Kh) + ((size_t)bh * SS + s) * 32 + (tid & 1) * 16;
        #pragma unroll
        for (int j = 0; j < 16; j++)
            Dh[j] = packfp2_hi(o[2*j], o[2*j + 1]);
    } else {
        #pragma unroll
        for (int i = 0; i < 32; i++)
            o[i] = Sg[m*66 + half + i] + sBias[half + i];
        size_t base = (size_t)bh * 64 * 1024 + ((m0 & 2047) >> 1) + (tid >> 2);
        #pragma unroll
        for (int i = 0; i < 32; i++) {
            float pv = __shfl_down_sync(0xFFFFFFFFu, o[i], 2);
            if (!(tid & 2)) {
                uint32_t hw, lw;
                packbf2(o[i], pv, hw, lw);
                g_Vh[base + (size_t)(half + i) * 1024] = hw;
                g_Vl[base + (size_t)(half + i) * 1024] = lw;
            }
        }
    }
}

__global__ __launch_bounds__(256, 2)
void o_pk(const float* __restrict__ bo, float* __restrict__ out) {
    extern __shared__ uint32_t smw[];
    int tid = threadIdx.x;
    int m0 = blockIdx.y * 128, n0 = blockIdx.x * 64;
    if (tid < 64) ((float*)(smw + W_BIAS))[tid] = bo[n0 + tid];
    __syncthreads();

    float acc[2][4][4] = {};
    size_t zo = (size_t)3 * HH * WPR;
    gemm_main(g_Ch, g_Cl, g_WTh + zo, g_WTl + zo, m0, n0, smw, acc);
    stage_acc(smw, acc);

    float* Sg = (float*)smw;
    const float* sBias = (const float*)(smw + W_BIAS);
    int m = tid >> 1;
    int half = (tid & 1) * 32;
    float* dst = out + (size_t)(m0 + m) * HH + n0 + half;
    #pragma unroll
    for (int i4 = 0; i4 < 8; i4++) {
        float4 v;
        v.x = Sg[m*66 + half + i4*4 + 0] + sBias[half + i4*4 + 0];
        v.y = Sg[m*66 + half + i4*4 + 1] + sBias[half + i4*4 + 1];
        v.z = Sg[m*66 + half + i4*4 + 2] + sBias[half + i4*4 + 2];
        v.w = Sg[m*66 + half + i4*4 + 3] + sBias[half + i4*4 + 3];
        *(float4*)(dst + i4*4) = v;
    }
}

// ---------------------------------------------------------------------------
// Flash attention v8: single-pass FP16 QK^T (8x less noise than bf16 —
// restores rel_err margin), 3-pass bf16 PV, ex2 softmax, 2 CTAs/SM,
// Q persistent (fp16, hi-only region), double-buffered cp.async.
// smem words: buf q at q*6912 {KH+0, VH+2304, VL+4608}; QH 13824 (4608);
// mask 18432 + q*64. Total 18560 w = 74.24 KB.
// ---------------------------------------------------------------------------
#define FV_BUF(q) ((q)*6912)
#define FV_QH 13824
#define FV_MSB(q) (18432 + (q)*64)
#define FLASH_SMEM (18560*4)

__global__ __launch_bounds__(256, 2)
void flash_pk(const float* __restrict__ mask) {
    extern __shared__ uint32_t smw[];
    const uint32_t sb = smem_u32(smw);
    int bh = blockIdx.y;
    int b = bh / NHH, h = bh % NHH;
    int sq0 = blockIdx.x * 128;
    const float* mkg = mask + (size_t)b * SS;
    int tid = threadIdx.x;
    int wid = tid >> 5, lane = tid & 31, g = lane >> 2, c = lane & 3;
    const int l8 = (lane >> 3) & 1, l16 = lane >> 4, l7 = lane & 7;

    const uint32_t* Khg0 = g_Kh + (size_t)bh * SS * 32;
    const uint32_t* Vhg0 = g_Vh + (size_t)bh * 64 * 1024;
    const uint32_t* Vlg0 = g_Vl + (size_t)bh * 64 * 1024;
    const int cr = tid >> 3, cu = tid & 7;   // staging row/quad

    const int qoff = (wid*16 + l8*8 + l7)*36 + l16*4;
    int koff[4];
    #pragma unroll
    for (int t = 0; t < 4; t++)
        koff[t] = (t*16 + l16*8 + l7)*36 + l8*4;   // same formula for K and V

    // prologue: issue K/V tile 0 into buf0 (async)
    {
        uint32_t kb = FV_BUF(0);
        #pragma unroll
        for (int it = 0; it < 2; it++) {
            int r = cr + it*32;
            uint32_t wo = (r*36 + cu*4)*4;
            cpa16(sb + kb*4          + wo, Khg0 + r*32 + cu*4);
            cpa16(sb + (kb + 2304)*4 + wo, Vhg0 + (size_t)r*1024 + cu*4);
            cpa16(sb + (kb + 4608)*4 + wo, Vlg0 + (size_t)r*1024 + cu*4);
        }
        if (tid < 16) cpa16(sb + (FV_MSB(0) + tid*4)*4, mkg + tid*4);
        CPA_COMMIT();
    }

    // stage Q (128 rows fp16, hi-only region): 1024 uint4 -> 4 iterations.
    {
        const uint32_t* Qhg = g_Qh + ((size_t)bh * SS + sq0) * 32;
        #pragma unroll
        for (int it = 0; it < 4; it++) {
            int idx = tid + it * 256;
            int r = idx >> 3, u = idx & 7;
            *(uint4*)(smw + FV_QH + r*36 + u*4) = *(const uint4*)(Qhg + r*32 + u*4);
        }
    }

    float oa[8][4] = {};
    float l0r = 0.0f, l1r = 0.0f;   // per-lane partial row sums

    for (int jt = 0; jt < 32; jt++) {
        const int cur = jt & 1;
        __syncthreads();   // compute on buf[1-cur] (jt-1) done; Q stores visible at jt=0
        if (jt < 31) {
            int jn = jt + 1;
            uint32_t kb = FV_BUF(1 - cur);
            const uint32_t* Khg = Khg0 + (size_t)jn*64*32 + cr*32 + cu*4;
            const uint32_t* Vhg = Vhg0 + jn*32 + (size_t)cr*1024 + cu*4;
            const uint32_t* Vlg = Vlg0 + jn*32 + (size_t)cr*1024 + cu*4;
            #pragma unroll
            for (int it = 0; it < 2; it++) {
                int r = cr + it*32;
                uint32_t wo = (r*36 + cu*4)*4;
                cpa16(sb + kb*4          + wo, Khg + it*32*32);
                cpa16(sb + (kb + 2304)*4 + wo, Vhg + (size_t)it*32*1024);
                cpa16(sb + (kb + 4608)*4 + wo, Vlg + (size_t)it*32*1024);
            }
            if (tid < 16) cpa16(sb + (FV_MSB(1 - cur) + tid*4)*4, mkg + jn*64 + tid*4);
        }
        CPA_COMMIT();
        if (jt < 31) CPA_WAIT1(); else CPA_WAIT0();
        __syncthreads();   // tile jt data visible to all threads

        const uint32_t KHb = FV_BUF(cur);
        const uint32_t VHb = KHb + 2304, VLb = KHb + 4608;
        const float* msf = (const float*)(smw + FV_MSB(cur));

        // --- S = Q @ K^T, single-pass fp16 (scores in log2 domain) ---
        float sv[8][4] = {};
        #pragma unroll
        for (int ks = 0; ks < 4; ks++) {
            int kk = ks * 8;
            uint32_t qh[4];
            ldsm4(qh, sb + (FV_QH + qoff + kk)*4);
            #pragma unroll
            for (int t = 0; t < 4; t++) {
                uint32_t bhf[4];
                ldsm4(bhf, sb + (KHb + koff[t] + kk)*4);
                mmafp2(sv[2*t],   qh, bhf[0], bhf[1]);
                mmafp2(sv[2*t+1], qh, bhf[2], bhf[3]);
            }
        }

        // --- softmax: p = ex2(s + mask_log2), accumulate lane sums ---
        #pragma unroll
        for (int nt = 0; nt < 8; nt++) {
            int col = nt*8 + 2*c;
            float ma = fmaf(msf[col],     14426.950408889634f, -14426.950408889634f);
            float mb = fmaf(msf[col + 1], 14426.950408889634f, -14426.950408889634f);
            sv[nt][0] = fex2(sv[nt][0] + ma); l0r += sv[nt][0];
            sv[nt][1] = fex2(sv[nt][1] + mb); l0r += sv[nt][1];
            sv[nt][2] = fex2(sv[nt][2] + ma); l1r += sv[nt][2];
            sv[nt][3] = fex2(sv[nt][3] + mb); l1r += sv[nt][3];
        }

        // --- O += P @ V (3-pass bf16); pack P per-ks inside the loop ---
        #pragma unroll
        for (int ks = 0; ks < 4; ks++) {
            uint32_t pah[4], pal[4];
            packbf2(sv[2*ks][0],   sv[2*ks][1],   pah[0], pal[0]);
            packbf2(sv[2*ks][2],   sv[2*ks][3],   pah[1], pal[1]);
            packbf2(sv[2*ks+1][0], sv[2*ks+1][1], pah[2], pal[2]);
            packbf2(sv[2*ks+1][2], sv[2*ks+1][3], pah[3], pal[3]);
            int kk = ks * 8;
            #pragma unroll
            for (int t = 0; t < 4; t++) {
                uint32_t vh[4], vl[4];
                ldsm4(vh, sb + (VHb + koff[t] + kk)*4);
                ldsm4(vl, sb + (VLb + koff[t] + kk)*4);
                mmabf2(oa[2*t],   pal, vh[0], vh[1]);
                mmabf2(oa[2*t+1], pal, vh[2], vh[3]);
                mmabf2(oa[2*t],   pah, vl[0], vl[1]);
                mmabf2(oa[2*t+1], pah, vl[2], vl[3]);
                mmabf2(oa[2*t],   pah, vh[0], vh[1]);
                mmabf2(oa[2*t+1], pah, vh[2], vh[3]);
            }
        }
    }

    // --- close lane sums (deferred), normalize, write ctx packed ---
    l0r += __shfl_xor_sync(0xFFFFFFFFu, l0r, 1);
    l0r += __shfl_xor_sync(0xFFFFFFFFu, l0r, 2);
    l1r += __shfl_xor_sync(0xFFFFFFFFu, l1r, 1);
    l1r += __shfl_xor_sync(0xFFFFFFFFu, l1r, 2);
    float inv0 = 1.0f / l0r, inv1 = 1.0f / l1r;
    int sA = sq0 + wid*16 + g, sB = sA + 8;
    size_t baseA = ((size_t)(b*SS + sA)) * WPR + h*32;
    size_t baseB = ((size_t)(b*SS + sB)) * WPR + h*32;
    #pragma unroll
    for (int nch = 0; nch < 8; nch++) {
        uint32_t hw, lw;
        packbf2(oa[nch][0] * inv0, oa[nch][1] * inv0, hw, lw);
        g_Ch[baseA + nch*4 + c] = hw; g_Cl[baseA + nch*4 + c] = lw;
        packbf2(oa[nch][2] * inv1, oa[nch][3] * inv1, hw, lw);
        g_Ch[baseB + nch*4 + c] = hw; g_Cl[baseB + nch*4 + c] = lw;
    }
}

extern "C" void kernel_launch(void* const* d_in, const int* in_sizes, int n_in,
                              void* d_out, int out_size) {
    const float* hs   = (const float*)d_in[0];
    const float* mask = (const float*)d_in[1];
    const float* Wq   = (const float*)d_in[2];
    const float* bq   = (const float*)d_in[3];
    const float* Wk   = (const float*)d_in[4];
    const float* bk   = (const float*)d_in[5];
    const float* Wv   = (const float*)d_in[6];
    const float* bv   = (const float*)d_in[7];
    const float* Wo   = (const float*)d_in[8];
    const float* bo   = (const float*)d_in[9];
    const float* cosp = (const float*)d_in[10];
    const float* sinp = (const float*)d_in[11];
    float* out = (float*)d_out;

    cudaFuncSetAttribute(qkv_pk,   cudaFuncAttributeMaxDynamicSharedMemorySize, GEMM_SMEM);
    cudaFuncSetAttribute(o_pk,     cudaFuncAttributeMaxDynamicSharedMemorySize, GEMM_SMEM);
    cudaFuncSetAttribute(flash_pk, cudaFuncAttributeMaxDynamicSharedMemorySize, FLASH_SMEM);

    pack_x<<<768, 256>>>(hs);
    transpose_pack_w<<<dim3(24, 24, 4), dim3(32, 8)>>>(Wq, Wk, Wv, Wo);
    qkv_pk<<<dim3(12, 32, 3), 256, GEMM_SMEM>>>(bq, bk, bv, cosp, sinp);
    flash_pk<<<dim3(16, 24), 256, FLASH_SMEM>>>(mask);
    o_pk<<<dim3(12, 32), 256, GEMM_SMEM>>>(bo, out);
}